// round 8
// baseline (speedup 1.0000x reference)
#include <cuda_runtime.h>
#include <cuda_fp16.h>
#include <mma.h>
#include <math.h>
#include <stdint.h>

using namespace nvcuda;

// ---------------- problem constants ----------------
#define HID    768
#define BATCH  4
#define SSYN   4096
#define SSEM   2048
#define SEMROWS 8192     // BATCH*SSEM
#define SYNROWS 16384    // BATCH*SSYN

// ---------------- scratch (device globals; no allocations allowed) --------
__device__ __half g_semh[SEMROWS*HID];
__device__ __half g_synh[SYNROWS*HID];
__device__ __half g_wt[6*HID*HID];        // transposed weights [out,in] -> [N,K]
__device__ __half g_q1[SEMROWS*HID];
__device__ __half g_k1[SYNROWS*HID];
__device__ __half g_q2[SYNROWS*HID];
__device__ __half g_k2[SEMROWS*HID];
__device__ __half g_v1t[HID*SYNROWS];     // V1^T [768, 16384]
__device__ __half g_v2t[HID*SEMROWS];     // V2^T [768, 8192]
__device__ float  g_s1[(long long)BATCH*SSEM*SSYN];   // fp32 scores
__device__ float  g_s2[(long long)BATCH*SSYN*SSEM];
__device__ __half g_p1[(long long)BATCH*SSEM*SSYN];   // fp16 probs
__device__ __half g_p2[(long long)BATCH*SSYN*SSEM];

struct H4 { __half2 a, b; };   // 8-byte packed 4x half

// ------ fp16 wmma GEMM, 128x128x64 tile, 3-stage cp.async, 1 sync/tile ----
// C = (A @ B^T (+bias)) * scale
// A row-major [M,K] (lda=K), B row-major [N,K] (row stride ldb), C row-major ldc=N.
// DUAL: blockIdx.z in {0,1} selects (B,bias,C) vs (B2,bias2,C2), same A.
// !DUAL: blockIdx.z is the batch index with strides sA/sB/sC.
constexpr int TM = 128, TN = 128, TK = 64;
constexpr int KP = 72;                        // padded halfs per tile row (144B)
constexpr int TILE_H = 128 * KP;              // 9216 halfs per operand
constexpr int STAGE_H = 2 * TILE_H;           // A+B per stage
constexpr int STAGE_BYTES = STAGE_H * 2;      // 36864
constexpr int NSTAGE = 3;
constexpr int SMEM_GEMM = NSTAGE * STAGE_BYTES + 512;  // 111104 B (2 CTAs/SM: 222208 < 228K)

__device__ __forceinline__ void cpa16(__half* dst, const __half* src) {
    unsigned d = (unsigned)__cvta_generic_to_shared(dst);
    asm volatile("cp.async.cg.shared.global [%0], [%1], 16;" :: "r"(d), "l"(src));
}

// BIASMODE: 0=none, 1=bias over columns (n), 2=bias over rows (m)
template<int BIASMODE, typename CT, bool DUAL>
__global__ __launch_bounds__(256, 2)
void gemm_fp16(const __half* __restrict__ A,
               const __half* __restrict__ B,  const __half* __restrict__ B2,
               const float* __restrict__ bias, const float* __restrict__ bias2,
               CT* __restrict__ C, CT* __restrict__ C2,
               int N, int K, int ldb,
               long long sA, long long sB, long long sC, float scale)
{
    extern __shared__ __align__(16) __half sm[];
    float* biassm = (float*)((char*)sm + NSTAGE * STAGE_BYTES);

    const int tid = threadIdx.x;
    const int wid = tid >> 5;
    const int wm  = wid & 1;               // warp row 0..1 (64 rows)
    const int wn  = wid >> 1;              // warp col 0..3 (32 cols)

    const __half* Bsel = B;
    const float*  bsel = bias;
    CT*           Csel = C;
    long long z = 0;
    if (DUAL) {
        if (blockIdx.z == 1) { Bsel = B2; bsel = bias2; Csel = C2; }
    } else {
        z = blockIdx.z;
    }

    const int n0 = blockIdx.x * TN;
    const long long row0 = (long long)blockIdx.y * TM;
    const __half* Ab = A + z * sA + row0 * K;
    const __half* Bb = Bsel + z * sB + (long long)n0 * ldb;
    CT*           Cb = Csel + z * sC;

    if (BIASMODE == 1 && tid < TN) biassm[tid] = bsel[n0 + tid];
    if (BIASMODE == 2 && tid < TM) biassm[tid] = bsel[row0 + tid];

    wmma::fragment<wmma::matrix_a, 16, 16, 16, __half, wmma::row_major> af[4];
    wmma::fragment<wmma::matrix_b, 16, 16, 16, __half, wmma::col_major> bf[2];
    wmma::fragment<wmma::accumulator, 16, 16, 16, float> cf[4][2];
    #pragma unroll
    for (int i = 0; i < 4; i++)
        #pragma unroll
        for (int j = 0; j < 2; j++)
            wmma::fill_fragment(cf[i][j], 0.0f);

    const int nt = K / TK;

    auto load_tiles = [&](int t, int stage) {
        const __half* Ag = Ab + (long long)t * TK;
        __half* da = sm + stage * STAGE_H;
        #pragma unroll
        for (int i = 0; i < 4; i++) {
            int idx = tid + (i << 8);
            int r = idx >> 3, c = (idx & 7) << 3;     // 8 halfs = 16B
            cpa16(da + r * KP + c, Ag + (long long)r * K + c);
        }
        const __half* Bg = Bb + (long long)t * TK;
        __half* db = da + TILE_H;
        #pragma unroll
        for (int i = 0; i < 4; i++) {
            int idx = tid + (i << 8);
            int r = idx >> 3, c = (idx & 7) << 3;
            cpa16(db + r * KP + c, Bg + (long long)r * ldb + c);
        }
    };

    // prologue: 2 stages in flight
    load_tiles(0, 0);
    asm volatile("cp.async.commit_group;");
    if (nt > 1) load_tiles(1, 1);
    asm volatile("cp.async.commit_group;");

    for (int t = 0; t < nt; t++) {
        // stage t is complete once at most 1 newer group remains outstanding
        asm volatile("cp.async.wait_group 1;");
        __syncthreads();   // also guards WAR: stage (t+2)%3 == stage (t-1)%3 compute done

        if (t + 2 < nt) load_tiles(t + 2, (t + 2) % NSTAGE);
        asm volatile("cp.async.commit_group;");   // one commit per iter keeps accounting exact

        const __half* Ad = sm + (t % NSTAGE) * STAGE_H;
        const __half* Bd = Ad + TILE_H;
        #pragma unroll
        for (int kk = 0; kk < 4; kk++) {
            #pragma unroll
            for (int i = 0; i < 4; i++)
                wmma::load_matrix_sync(af[i], Ad + (wm * 64 + i * 16) * KP + kk * 16, KP);
            #pragma unroll
            for (int j = 0; j < 2; j++)
                wmma::load_matrix_sync(bf[j], Bd + (wn * 32 + j * 16) * KP + kk * 16, KP);
            #pragma unroll
            for (int i = 0; i < 4; i++)
                #pragma unroll
                for (int j = 0; j < 2; j++)
                    wmma::mma_sync(cf[i][j], af[i], bf[j], cf[i][j]);
        }
    }
    __syncthreads();   // all compute done before smem is reused as Cs

    // ---- epilogue: stage fp32 accumulators through smem, fused bias+scale ----
    float* Cs = (float*)sm;    // [128][136] = 69632 B
    #pragma unroll
    for (int i = 0; i < 4; i++)
        #pragma unroll
        for (int j = 0; j < 2; j++)
            wmma::store_matrix_sync(Cs + (wm * 64 + i * 16) * 136 + wn * 32 + j * 16,
                                    cf[i][j], 136, wmma::mem_row_major);
    __syncthreads();

    if (sizeof(CT) == 4) {
        // fp32 output
        #pragma unroll
        for (int i = 0; i < 16; i++) {
            int idx = tid + (i << 8);
            int r = idx >> 5, c = (idx & 31) << 2;
            float4 v = *reinterpret_cast<const float4*>(Cs + r * 136 + c);
            if (BIASMODE == 1) {
                v.x += biassm[c + 0]; v.y += biassm[c + 1];
                v.z += biassm[c + 2]; v.w += biassm[c + 3];
            }
            if (BIASMODE == 2) {
                float rb = biassm[r];
                v.x += rb; v.y += rb; v.z += rb; v.w += rb;
            }
            v.x *= scale; v.y *= scale; v.z *= scale; v.w *= scale;
            *reinterpret_cast<float4*>((float*)Cb + (row0 + r) * N + n0 + c) = v;
        }
    } else {
        // fp16 output, 8 halfs per chunk
        #pragma unroll
        for (int i = 0; i < 8; i++) {
            int idx = tid + (i << 8);
            int r = idx >> 4, c = (idx & 15) << 3;
            float4 v0 = *reinterpret_cast<const float4*>(Cs + r * 136 + c);
            float4 v1 = *reinterpret_cast<const float4*>(Cs + r * 136 + c + 4);
            if (BIASMODE == 1) {
                v0.x += biassm[c + 0]; v0.y += biassm[c + 1];
                v0.z += biassm[c + 2]; v0.w += biassm[c + 3];
                v1.x += biassm[c + 4]; v1.y += biassm[c + 5];
                v1.z += biassm[c + 6]; v1.w += biassm[c + 7];
            }
            if (BIASMODE == 2) {
                float rb = biassm[r];
                v0.x += rb; v0.y += rb; v0.z += rb; v0.w += rb;
                v1.x += rb; v1.y += rb; v1.z += rb; v1.w += rb;
            }
            v0.x *= scale; v0.y *= scale; v0.z *= scale; v0.w *= scale;
            v1.x *= scale; v1.y *= scale; v1.z *= scale; v1.w *= scale;
            __half2 h0 = __floats2half2_rn(v0.x, v0.y);
            __half2 h1 = __floats2half2_rn(v0.z, v0.w);
            __half2 h2 = __floats2half2_rn(v1.x, v1.y);
            __half2 h3 = __floats2half2_rn(v1.z, v1.w);
            uint4 pk;
            pk.x = *(unsigned*)&h0; pk.y = *(unsigned*)&h1;
            pk.z = *(unsigned*)&h2; pk.w = *(unsigned*)&h3;
            *reinterpret_cast<uint4*>((__half*)Cb + (row0 + r) * N + n0 + c) = pk;
        }
    }
}

// ---------------- elementwise fp32 -> fp16 ----------------
__global__ __launch_bounds__(256)
void cvt_half(const float* __restrict__ in, __half* __restrict__ out, int n)
{
    int i = (blockIdx.x * 256 + threadIdx.x) * 4;
    if (i < n) {
        float4 v = *reinterpret_cast<const float4*>(in + i);
        H4 h; __half2* hp = (__half2*)&h;
        hp[0] = __floats2half2_rn(v.x, v.y);
        hp[1] = __floats2half2_rn(v.z, v.w);
        *reinterpret_cast<H4*>(out + i) = h;
    }
}

// -------- batched transpose fp32 -> fp16 (all 6 weights in one launch) ----
struct WSet { const float* in[6]; };
__global__ __launch_bounds__(256)
void transpose_h6(WSet ws, __half* __restrict__ out)
{
    __shared__ float ts[32][33];
    const int R = HID, C = HID;
    const float* in = ws.in[blockIdx.z];
    __half* o = out + (long long)blockIdx.z * HID * HID;
    int tx = threadIdx.x & 31, ty = threadIdx.x >> 5;
    int c0 = blockIdx.x * 32, r0 = blockIdx.y * 32;
    #pragma unroll
    for (int j = 0; j < 4; j++)
        ts[ty + j * 8][tx] = in[(long long)(r0 + ty + j * 8) * C + c0 + tx];
    __syncthreads();
    #pragma unroll
    for (int j = 0; j < 4; j++)
        o[(long long)(c0 + ty + j * 8) * R + r0 + tx] = __float2half_rn(ts[tx][ty + j * 8]);
}

// ---------------- row softmax: fp32 scores in, fp16 probs out -------------
template<int NV>
__global__ __launch_bounds__(256)
void softmax_rows(const float* __restrict__ S, __half* __restrict__ P, int ncols)
{
    __shared__ float red[8];
    const float* p = S + (long long)blockIdx.x * ncols;
    __half* q = P + (long long)blockIdx.x * ncols;
    const int tid = threadIdx.x;

    float4 v[NV];
    float m = -3.4e38f;
    #pragma unroll
    for (int i = 0; i < NV; i++) {
        v[i] = reinterpret_cast<const float4*>(p)[tid + (i << 8)];
        m = fmaxf(m, fmaxf(fmaxf(v[i].x, v[i].y), fmaxf(v[i].z, v[i].w)));
    }
    #pragma unroll
    for (int o = 16; o > 0; o >>= 1) m = fmaxf(m, __shfl_xor_sync(0xffffffffu, m, o));
    if ((tid & 31) == 0) red[tid >> 5] = m;
    __syncthreads();
    m = red[0];
    #pragma unroll
    for (int w = 1; w < 8; w++) m = fmaxf(m, red[w]);
    __syncthreads();

    float s = 0.0f;
    #pragma unroll
    for (int i = 0; i < NV; i++) {
        v[i].x = __expf(v[i].x - m); s += v[i].x;
        v[i].y = __expf(v[i].y - m); s += v[i].y;
        v[i].z = __expf(v[i].z - m); s += v[i].z;
        v[i].w = __expf(v[i].w - m); s += v[i].w;
    }
    #pragma unroll
    for (int o = 16; o > 0; o >>= 1) s += __shfl_xor_sync(0xffffffffu, s, o);
    if ((tid & 31) == 0) red[tid >> 5] = s;
    __syncthreads();
    s = red[0];
    #pragma unroll
    for (int w = 1; w < 8; w++) s += red[w];

    const float inv = 1.0f / s;
    #pragma unroll
    for (int i = 0; i < NV; i++) {
        H4 h; __half2* hp = (__half2*)&h;
        hp[0] = __floats2half2_rn(v[i].x * inv, v[i].y * inv);
        hp[1] = __floats2half2_rn(v[i].z * inv, v[i].w * inv);
        reinterpret_cast<H4*>(q)[tid + (i << 8)] = h;
    }
}

// ---------------- launcher ----------------
extern "C" void kernel_launch(void* const* d_in, const int* in_sizes, int n_in,
                              void* d_out, int out_size)
{
    const float* syn = (const float*)d_in[0];   // [4, 4096, 768]
    const float* sem = (const float*)d_in[1];   // [4, 2048, 768]
    const float* Wq1 = (const float*)d_in[2];  const float* bq1 = (const float*)d_in[3];
    const float* Wk1 = (const float*)d_in[4];  const float* bk1 = (const float*)d_in[5];
    const float* Wv1 = (const float*)d_in[6];  const float* bv1 = (const float*)d_in[7];
    const float* Wq2 = (const float*)d_in[8];  const float* bq2 = (const float*)d_in[9];
    const float* Wk2 = (const float*)d_in[10]; const float* bk2 = (const float*)d_in[11];
    const float* Wv2 = (const float*)d_in[12]; const float* bv2 = (const float*)d_in[13];

    float* o1 = (float*)d_out;                      // enhanced_semantic [4,2048,768]
    float* o2 = o1 + (long long)SEMROWS * HID;      // enhanced_syntax   [4,4096,768]

    __half *semh, *synh, *wt, *q1, *k1, *q2, *k2, *v1t, *v2t, *p1, *p2;
    float *s1, *s2;
    cudaGetSymbolAddress((void**)&semh, g_semh);
    cudaGetSymbolAddress((void**)&synh, g_synh);
    cudaGetSymbolAddress((void**)&wt, g_wt);
    cudaGetSymbolAddress((void**)&q1, g_q1);
    cudaGetSymbolAddress((void**)&k1, g_k1);
    cudaGetSymbolAddress((void**)&q2, g_q2);
    cudaGetSymbolAddress((void**)&k2, g_k2);
    cudaGetSymbolAddress((void**)&v1t, g_v1t);
    cudaGetSymbolAddress((void**)&v2t, g_v2t);
    cudaGetSymbolAddress((void**)&s1, g_s1);
    cudaGetSymbolAddress((void**)&s2, g_s2);
    cudaGetSymbolAddress((void**)&p1, g_p1);
    cudaGetSymbolAddress((void**)&p2, g_p2);

    cudaFuncSetAttribute(gemm_fp16<1, __half, true>,
                         cudaFuncAttributeMaxDynamicSharedMemorySize, SMEM_GEMM);
    cudaFuncSetAttribute(gemm_fp16<2, __half, false>,
                         cudaFuncAttributeMaxDynamicSharedMemorySize, SMEM_GEMM);
    cudaFuncSetAttribute(gemm_fp16<0, float, false>,
                         cudaFuncAttributeMaxDynamicSharedMemorySize, SMEM_GEMM);

    const float scale = 1.0f / sqrtf((float)HID);
    const long long WN = (long long)HID * HID;

    // ---- convert inputs; transpose+convert all weights in one launch ----
    cvt_half<<<SEMROWS * HID / 1024, 256>>>(sem, semh, SEMROWS * HID);
    cvt_half<<<SYNROWS * HID / 1024, 256>>>(syn, synh, SYNROWS * HID);
    WSet ws;
    ws.in[0] = Wq1; ws.in[1] = Wk1; ws.in[2] = Wv1;
    ws.in[3] = Wq2; ws.in[4] = Wk2; ws.in[5] = Wv2;
    transpose_h6<<<dim3(HID / 32, HID / 32, 6), 256>>>(ws, wt);

    // ---- Q/K projections, dual-output (shared A, z selects weight/out) ----
    gemm_fp16<1, __half, true><<<dim3(HID/TN, SEMROWS/TM, 2), 256, SMEM_GEMM>>>(
        semh, wt + 0 * WN, wt + 4 * WN, bq1, bk2, q1, k2,
        HID, HID, HID, 0, 0, 0, 1.0f);
    gemm_fp16<1, __half, true><<<dim3(HID/TN, SYNROWS/TM, 2), 256, SMEM_GEMM>>>(
        synh, wt + 1 * WN, wt + 3 * WN, bk1, bq2, k1, q2,
        HID, HID, HID, 0, 0, 0, 1.0f);

    // ---- V projections, produced TRANSPOSED: Vt[h,s] = Wt_v[h,k] X[s,k] + b[h] ----
    gemm_fp16<2, __half, false><<<dim3(SYNROWS/TN, HID/TM, 1), 256, SMEM_GEMM>>>(
        wt + 2 * WN, synh, nullptr, bv1, nullptr, v1t, nullptr,
        SYNROWS, HID, HID, 0, 0, 0, 1.0f);
    gemm_fp16<2, __half, false><<<dim3(SEMROWS/TN, HID/TM, 1), 256, SMEM_GEMM>>>(
        wt + 5 * WN, semh, nullptr, bv2, nullptr, v2t, nullptr,
        SEMROWS, HID, HID, 0, 0, 0, 1.0f);

    // ---- scores (fp32 out): S[q,k] = Q[q,h] K[k,h] * scale, batched z=4 ----
    gemm_fp16<0, float, false><<<dim3(SSYN/TN, SSEM/TM, BATCH), 256, SMEM_GEMM>>>(
        q1, k1, nullptr, nullptr, nullptr, s1, nullptr,
        SSYN, HID, HID,
        (long long)SSEM*HID, (long long)SSYN*HID, (long long)SSEM*SSYN, scale);
    gemm_fp16<0, float, false><<<dim3(SSEM/TN, SSYN/TM, BATCH), 256, SMEM_GEMM>>>(
        q2, k2, nullptr, nullptr, nullptr, s2, nullptr,
        SSEM, HID, HID,
        (long long)SSYN*HID, (long long)SSEM*HID, (long long)SSYN*SSEM, scale);

    // ---- softmax over keys: fp32 in, fp16 probs out ----
    softmax_rows<4><<<SEMROWS, 256>>>(s1, p1, SSYN);
    softmax_rows<2><<<SYNROWS, 256>>>(s2, p2, SSEM);

    // ---- output: O[q,h] = P[q,s] Vt[h,s], batched z=4 (Vt batch-sliced on K) ----
    gemm_fp16<0, float, false><<<dim3(HID/TN, SSEM/TM, BATCH), 256, SMEM_GEMM>>>(
        p1, v1t, nullptr, nullptr, nullptr, o1, nullptr,
        HID, SSYN, SYNROWS,
        (long long)SSEM*SSYN, (long long)SSYN, (long long)SSEM*HID, 1.0f);
    gemm_fp16<0, float, false><<<dim3(HID/TN, SSYN/TM, BATCH), 256, SMEM_GEMM>>>(
        p2, v2t, nullptr, nullptr, nullptr, o2, nullptr,
        HID, SSEM, SEMROWS,
        (long long)SSYN*SSEM, (long long)SSEM, (long long)SSYN*HID, 1.0f);
}

// round 9
// speedup vs baseline: 1.0930x; 1.0930x over previous
#include <cuda_runtime.h>
#include <cuda_fp16.h>
#include <mma.h>
#include <math.h>
#include <stdint.h>

using namespace nvcuda;

// ---------------- problem constants ----------------
#define HID    768
#define BATCH  4
#define SSYN   4096
#define SSEM   2048
#define SEMROWS 8192     // BATCH*SSEM
#define SYNROWS 16384    // BATCH*SSYN

// ---------------- scratch (device globals; no allocations allowed) --------
__device__ __half g_semh[SEMROWS*HID];
__device__ __half g_synh[SYNROWS*HID];
__device__ __half g_wt[6*HID*HID];        // transposed weights [out,in] -> [N,K]
__device__ __half g_q1[SEMROWS*HID];
__device__ __half g_k1[SYNROWS*HID];
__device__ __half g_q2[SYNROWS*HID];
__device__ __half g_k2[SEMROWS*HID];
__device__ __half g_v1t[HID*SYNROWS];     // V1^T [768, 16384]
__device__ __half g_v2t[HID*SEMROWS];     // V2^T [768, 8192]
__device__ __half g_p1[(long long)BATCH*SSEM*SSYN];   // fp16 E = exp(scores)
__device__ __half g_p2[(long long)BATCH*SSYN*SSEM];
__device__ float  g_part1[32 * SEMROWS];  // per-n-tile row partial sums
__device__ float  g_part2[16 * SYNROWS];
__device__ float  g_inv1[SEMROWS];        // 1 / rowsum
__device__ float  g_inv2[SYNROWS];

struct H4 { __half2 a, b; };

// ---- fp16 wmma GEMM, 128x128x64 tile, 2-stage cp.async double buffer ----
// C = f(A @ B^T) ; A row-major [M,K], B row-major [N,K] (stride ldb), C ldc=N.
// BIASMODE: 0=none, 1=col bias, 2=row bias, 3=row SCALE (fp32 out), 4=EXP-out fp16 + row partials
// DUAL: blockIdx.z selects (B,bias,C) vs (B2,bias2,C2); else z = batch index.
constexpr int TM = 128, TN = 128, TK = 64;
constexpr int KP = 72;                        // padded halfs per tile row (144B)
constexpr int TILE_H = 128 * KP;
constexpr int STAGE_H = 2 * TILE_H;
constexpr int STAGE_BYTES = STAGE_H * 2;      // 36864
constexpr int SMEM_GEMM = 2 * STAGE_BYTES + 512;  // 74240 B

__device__ __forceinline__ void cpa16(__half* dst, const __half* src) {
    unsigned d = (unsigned)__cvta_generic_to_shared(dst);
    asm volatile("cp.async.cg.shared.global [%0], [%1], 16;" :: "r"(d), "l"(src));
}

template<int BIASMODE, typename CT, bool DUAL>
__global__ __launch_bounds__(256, 2)
void gemm_fp16(const __half* __restrict__ A,
               const __half* __restrict__ B,  const __half* __restrict__ B2,
               const float* __restrict__ bias, const float* __restrict__ bias2,
               CT* __restrict__ C, CT* __restrict__ C2,
               int N, int K, int ldb,
               long long sA, long long sB, long long sC, float scale,
               float* __restrict__ part, int Mb,
               const float* __restrict__ rowscale, long long sR)
{
    extern __shared__ __align__(16) __half sm[];
    float* biassm = (float*)((char*)sm + 2 * STAGE_BYTES);

    const int tid = threadIdx.x;
    const int wid = tid >> 5;
    const int wm  = wid & 1;               // warp row 0..1 (64 rows)
    const int wn  = wid >> 1;              // warp col 0..3 (32 cols)

    const __half* Bsel = B;
    const float*  bsel = bias;
    CT*           Csel = C;
    long long z = 0;
    if (DUAL) {
        if (blockIdx.z == 1) { Bsel = B2; bsel = bias2; Csel = C2; }
    } else {
        z = blockIdx.z;
    }

    const int n0 = blockIdx.x * TN;
    const long long row0 = (long long)blockIdx.y * TM;
    const __half* Ab = A + z * sA + row0 * K;
    const __half* Bb = Bsel + z * sB + (long long)n0 * ldb;
    CT*           Cb = Csel + z * sC;

    if (BIASMODE == 1 && tid < TN) biassm[tid] = bsel[n0 + tid];
    if (BIASMODE == 2 && tid < TM) biassm[tid] = bsel[row0 + tid];
    if (BIASMODE == 3 && tid < TM) biassm[tid] = rowscale[z * sR + row0 + tid];

    wmma::fragment<wmma::matrix_a, 16, 16, 16, __half, wmma::row_major> af[4];
    wmma::fragment<wmma::matrix_b, 16, 16, 16, __half, wmma::col_major> bf[2];
    wmma::fragment<wmma::accumulator, 16, 16, 16, float> cf[4][2];
    #pragma unroll
    for (int i = 0; i < 4; i++)
        #pragma unroll
        for (int j = 0; j < 2; j++)
            wmma::fill_fragment(cf[i][j], 0.0f);

    const int nt = K / TK;

    auto load_tiles = [&](int t, int stage) {
        const __half* Ag = Ab + (long long)t * TK;
        __half* da = sm + stage * STAGE_H;
        #pragma unroll
        for (int i = 0; i < 4; i++) {
            int idx = tid + (i << 8);
            int r = idx >> 3, c = (idx & 7) << 3;
            cpa16(da + r * KP + c, Ag + (long long)r * K + c);
        }
        const __half* Bg = Bb + (long long)t * TK;
        __half* db = da + TILE_H;
        #pragma unroll
        for (int i = 0; i < 4; i++) {
            int idx = tid + (i << 8);
            int r = idx >> 3, c = (idx & 7) << 3;
            cpa16(db + r * KP + c, Bg + (long long)r * ldb + c);
        }
    };

    load_tiles(0, 0);
    asm volatile("cp.async.commit_group;");

    for (int t = 0; t < nt; t++) {
        if (t + 1 < nt) load_tiles(t + 1, (t + 1) & 1);
        asm volatile("cp.async.commit_group;");
        if (t + 1 < nt)
            asm volatile("cp.async.wait_group 1;");
        else
            asm volatile("cp.async.wait_group 0;");
        __syncthreads();

        const __half* Ad = sm + (t & 1) * STAGE_H;
        const __half* Bd = Ad + TILE_H;
        #pragma unroll
        for (int kk = 0; kk < 4; kk++) {
            #pragma unroll
            for (int i = 0; i < 4; i++)
                wmma::load_matrix_sync(af[i], Ad + (wm * 64 + i * 16) * KP + kk * 16, KP);
            #pragma unroll
            for (int j = 0; j < 2; j++)
                wmma::load_matrix_sync(bf[j], Bd + (wn * 32 + j * 16) * KP + kk * 16, KP);
            #pragma unroll
            for (int i = 0; i < 4; i++)
                #pragma unroll
                for (int j = 0; j < 2; j++)
                    wmma::mma_sync(cf[i][j], af[i], bf[j], cf[i][j]);
        }
        __syncthreads();
    }

    // ---- epilogue: stage fp32 accumulators through smem ----
    float* Cs = (float*)sm;    // [128][136]
    #pragma unroll
    for (int i = 0; i < 4; i++)
        #pragma unroll
        for (int j = 0; j < 2; j++)
            wmma::store_matrix_sync(Cs + (wm * 64 + i * 16) * 136 + wn * 32 + j * 16,
                                    cf[i][j], 136, wmma::mem_row_major);
    __syncthreads();

    if (sizeof(CT) == 4) {
        // fp32 output (modes 0, 3)
        #pragma unroll
        for (int i = 0; i < 16; i++) {
            int idx = tid + (i << 8);
            int r = idx >> 5, c = (idx & 31) << 2;
            float4 v = *reinterpret_cast<const float4*>(Cs + r * 136 + c);
            if (BIASMODE == 1) {
                v.x += biassm[c + 0]; v.y += biassm[c + 1];
                v.z += biassm[c + 2]; v.w += biassm[c + 3];
            }
            if (BIASMODE == 2) {
                float rb = biassm[r];
                v.x += rb; v.y += rb; v.z += rb; v.w += rb;
            }
            if (BIASMODE == 3) {
                float rb = biassm[r];
                v.x *= rb; v.y *= rb; v.z *= rb; v.w *= rb;
            }
            v.x *= scale; v.y *= scale; v.z *= scale; v.w *= scale;
            *reinterpret_cast<float4*>((float*)Cb + (row0 + r) * N + n0 + c) = v;
        }
    } else if (BIASMODE == 4) {
        // EXP output: E = exp(score*scale) in fp16; also row partial sums.
        #pragma unroll
        for (int i = 0; i < 8; i++) {
            int idx = tid + (i << 8);
            int r = idx >> 4, c = (idx & 15) << 3;
            float4 v0 = *reinterpret_cast<const float4*>(Cs + r * 136 + c);
            float4 v1 = *reinterpret_cast<const float4*>(Cs + r * 136 + c + 4);
            v0.x = __expf(v0.x * scale); v0.y = __expf(v0.y * scale);
            v0.z = __expf(v0.z * scale); v0.w = __expf(v0.w * scale);
            v1.x = __expf(v1.x * scale); v1.y = __expf(v1.y * scale);
            v1.z = __expf(v1.z * scale); v1.w = __expf(v1.w * scale);
            // write exp'ed values back for the row-sum pass
            *reinterpret_cast<float4*>(Cs + r * 136 + c) = v0;
            *reinterpret_cast<float4*>(Cs + r * 136 + c + 4) = v1;
            __half2 h0 = __floats2half2_rn(v0.x, v0.y);
            __half2 h1 = __floats2half2_rn(v0.z, v0.w);
            __half2 h2 = __floats2half2_rn(v1.x, v1.y);
            __half2 h3 = __floats2half2_rn(v1.z, v1.w);
            uint4 pk;
            pk.x = *(unsigned*)&h0; pk.y = *(unsigned*)&h1;
            pk.z = *(unsigned*)&h2; pk.w = *(unsigned*)&h3;
            *reinterpret_cast<uint4*>((__half*)Cb + (row0 + r) * N + n0 + c) = pk;
        }
        __syncthreads();
        if (tid < TM) {
            const float* rp = Cs + tid * 136;
            float s = 0.0f;
            #pragma unroll
            for (int c4 = 0; c4 < 32; c4++) {
                float4 v = *reinterpret_cast<const float4*>(rp + (c4 << 2));
                s += v.x + v.y + v.z + v.w;
            }
            part[(long long)blockIdx.x * ((long long)gridDim.z * Mb)
                 + z * Mb + row0 + tid] = s;
        }
    } else {
        // fp16 output (modes 1, 2)
        #pragma unroll
        for (int i = 0; i < 8; i++) {
            int idx = tid + (i << 8);
            int r = idx >> 4, c = (idx & 15) << 3;
            float4 v0 = *reinterpret_cast<const float4*>(Cs + r * 136 + c);
            float4 v1 = *reinterpret_cast<const float4*>(Cs + r * 136 + c + 4);
            if (BIASMODE == 1) {
                v0.x += biassm[c + 0]; v0.y += biassm[c + 1];
                v0.z += biassm[c + 2]; v0.w += biassm[c + 3];
                v1.x += biassm[c + 4]; v1.y += biassm[c + 5];
                v1.z += biassm[c + 6]; v1.w += biassm[c + 7];
            }
            if (BIASMODE == 2) {
                float rb = biassm[r];
                v0.x += rb; v0.y += rb; v0.z += rb; v0.w += rb;
                v1.x += rb; v1.y += rb; v1.z += rb; v1.w += rb;
            }
            v0.x *= scale; v0.y *= scale; v0.z *= scale; v0.w *= scale;
            v1.x *= scale; v1.y *= scale; v1.z *= scale; v1.w *= scale;
            __half2 h0 = __floats2half2_rn(v0.x, v0.y);
            __half2 h1 = __floats2half2_rn(v0.z, v0.w);
            __half2 h2 = __floats2half2_rn(v1.x, v1.y);
            __half2 h3 = __floats2half2_rn(v1.z, v1.w);
            uint4 pk;
            pk.x = *(unsigned*)&h0; pk.y = *(unsigned*)&h1;
            pk.z = *(unsigned*)&h2; pk.w = *(unsigned*)&h3;
            *reinterpret_cast<uint4*>((__half*)Cb + (row0 + r) * N + n0 + c) = pk;
        }
    }
}

// ---------------- rowsum reduce: inv[q] = 1 / sum_i part[i][q] ------------
__global__ __launch_bounds__(256)
void rsum_inv(const float* __restrict__ part, float* __restrict__ inv,
              int nparts, int rows)
{
    int q = blockIdx.x * 256 + threadIdx.x;
    if (q < rows) {
        float s = 0.0f;
        for (int i = 0; i < nparts; i++) s += part[(long long)i * rows + q];
        inv[q] = 1.0f / s;
    }
}

// ---------------- elementwise fp32 -> fp16 ----------------
__global__ __launch_bounds__(256)
void cvt_half(const float* __restrict__ in, __half* __restrict__ out, int n)
{
    int i = (blockIdx.x * 256 + threadIdx.x) * 4;
    if (i < n) {
        float4 v = *reinterpret_cast<const float4*>(in + i);
        H4 h; __half2* hp = (__half2*)&h;
        hp[0] = __floats2half2_rn(v.x, v.y);
        hp[1] = __floats2half2_rn(v.z, v.w);
        *reinterpret_cast<H4*>(out + i) = h;
    }
}

// -------- batched transpose fp32 -> fp16 (all 6 weights in one launch) ----
struct WSet { const float* in[6]; };
__global__ __launch_bounds__(256)
void transpose_h6(WSet ws, __half* __restrict__ out)
{
    __shared__ float ts[32][33];
    const int R = HID, C = HID;
    const float* in = ws.in[blockIdx.z];
    __half* o = out + (long long)blockIdx.z * HID * HID;
    int tx = threadIdx.x & 31, ty = threadIdx.x >> 5;
    int c0 = blockIdx.x * 32, r0 = blockIdx.y * 32;
    #pragma unroll
    for (int j = 0; j < 4; j++)
        ts[ty + j * 8][tx] = in[(long long)(r0 + ty + j * 8) * C + c0 + tx];
    __syncthreads();
    #pragma unroll
    for (int j = 0; j < 4; j++)
        o[(long long)(c0 + ty + j * 8) * R + r0 + tx] = __float2half_rn(ts[tx][ty + j * 8]);
}

// ---------------- launcher ----------------
extern "C" void kernel_launch(void* const* d_in, const int* in_sizes, int n_in,
                              void* d_out, int out_size)
{
    const float* syn = (const float*)d_in[0];   // [4, 4096, 768]
    const float* sem = (const float*)d_in[1];   // [4, 2048, 768]
    const float* Wq1 = (const float*)d_in[2];  const float* bq1 = (const float*)d_in[3];
    const float* Wk1 = (const float*)d_in[4];  const float* bk1 = (const float*)d_in[5];
    const float* Wv1 = (const float*)d_in[6];  const float* bv1 = (const float*)d_in[7];
    const float* Wq2 = (const float*)d_in[8];  const float* bq2 = (const float*)d_in[9];
    const float* Wk2 = (const float*)d_in[10]; const float* bk2 = (const float*)d_in[11];
    const float* Wv2 = (const float*)d_in[12]; const float* bv2 = (const float*)d_in[13];

    float* o1 = (float*)d_out;                      // enhanced_semantic [4,2048,768]
    float* o2 = o1 + (long long)SEMROWS * HID;      // enhanced_syntax   [4,4096,768]

    __half *semh, *synh, *wt, *q1, *k1, *q2, *k2, *v1t, *v2t, *p1, *p2;
    float *part1, *part2, *inv1, *inv2;
    cudaGetSymbolAddress((void**)&semh, g_semh);
    cudaGetSymbolAddress((void**)&synh, g_synh);
    cudaGetSymbolAddress((void**)&wt, g_wt);
    cudaGetSymbolAddress((void**)&q1, g_q1);
    cudaGetSymbolAddress((void**)&k1, g_k1);
    cudaGetSymbolAddress((void**)&q2, g_q2);
    cudaGetSymbolAddress((void**)&k2, g_k2);
    cudaGetSymbolAddress((void**)&v1t, g_v1t);
    cudaGetSymbolAddress((void**)&v2t, g_v2t);
    cudaGetSymbolAddress((void**)&p1, g_p1);
    cudaGetSymbolAddress((void**)&p2, g_p2);
    cudaGetSymbolAddress((void**)&part1, g_part1);
    cudaGetSymbolAddress((void**)&part2, g_part2);
    cudaGetSymbolAddress((void**)&inv1, g_inv1);
    cudaGetSymbolAddress((void**)&inv2, g_inv2);

    cudaFuncSetAttribute(gemm_fp16<1, __half, true>,
                         cudaFuncAttributeMaxDynamicSharedMemorySize, SMEM_GEMM);
    cudaFuncSetAttribute(gemm_fp16<2, __half, false>,
                         cudaFuncAttributeMaxDynamicSharedMemorySize, SMEM_GEMM);
    cudaFuncSetAttribute(gemm_fp16<4, __half, false>,
                         cudaFuncAttributeMaxDynamicSharedMemorySize, SMEM_GEMM);
    cudaFuncSetAttribute(gemm_fp16<3, float, false>,
                         cudaFuncAttributeMaxDynamicSharedMemorySize, SMEM_GEMM);

    const float scale = 1.0f / sqrtf((float)HID);
    const long long WN = (long long)HID * HID;

    // ---- convert inputs; transpose+convert all weights in one launch ----
    cvt_half<<<SEMROWS * HID / 1024, 256>>>(sem, semh, SEMROWS * HID);
    cvt_half<<<SYNROWS * HID / 1024, 256>>>(syn, synh, SYNROWS * HID);
    WSet ws;
    ws.in[0] = Wq1; ws.in[1] = Wk1; ws.in[2] = Wv1;
    ws.in[3] = Wq2; ws.in[4] = Wk2; ws.in[5] = Wv2;
    transpose_h6<<<dim3(HID / 32, HID / 32, 6), 256>>>(ws, wt);

    // ---- Q/K projections, dual-output (shared A, z selects weight/out) ----
    gemm_fp16<1, __half, true><<<dim3(HID/TN, SEMROWS/TM, 2), 256, SMEM_GEMM>>>(
        semh, wt + 0 * WN, wt + 4 * WN, bq1, bk2, q1, k2,
        HID, HID, HID, 0, 0, 0, 1.0f, nullptr, 0, nullptr, 0);
    gemm_fp16<1, __half, true><<<dim3(HID/TN, SYNROWS/TM, 2), 256, SMEM_GEMM>>>(
        synh, wt + 1 * WN, wt + 3 * WN, bk1, bq2, k1, q2,
        HID, HID, HID, 0, 0, 0, 1.0f, nullptr, 0, nullptr, 0);

    // ---- V projections, produced TRANSPOSED: Vt[h,s] = Wt_v[h,k] X[s,k] + b[h] ----
    gemm_fp16<2, __half, false><<<dim3(SYNROWS/TN, HID/TM, 1), 256, SMEM_GEMM>>>(
        wt + 2 * WN, synh, nullptr, bv1, nullptr, v1t, nullptr,
        SYNROWS, HID, HID, 0, 0, 0, 1.0f, nullptr, 0, nullptr, 0);
    gemm_fp16<2, __half, false><<<dim3(SEMROWS/TN, HID/TM, 1), 256, SMEM_GEMM>>>(
        wt + 5 * WN, semh, nullptr, bv2, nullptr, v2t, nullptr,
        SEMROWS, HID, HID, 0, 0, 0, 1.0f, nullptr, 0, nullptr, 0);

    // ---- scores fused with exp: E = exp(QK^T * scale) fp16 + row partials ----
    gemm_fp16<4, __half, false><<<dim3(SSYN/TN, SSEM/TM, BATCH), 256, SMEM_GEMM>>>(
        q1, k1, nullptr, nullptr, nullptr, p1, nullptr,
        SSYN, HID, HID,
        (long long)SSEM*HID, (long long)SSYN*HID, (long long)SSEM*SSYN, scale,
        part1, SSEM, nullptr, 0);
    gemm_fp16<4, __half, false><<<dim3(SSEM/TN, SSYN/TM, BATCH), 256, SMEM_GEMM>>>(
        q2, k2, nullptr, nullptr, nullptr, p2, nullptr,
        SSEM, HID, HID,
        (long long)SSYN*HID, (long long)SSEM*HID, (long long)SSYN*SSEM, scale,
        part2, SSYN, nullptr, 0);

    // ---- inverse row sums ----
    rsum_inv<<<SEMROWS / 256, 256>>>(part1, inv1, SSYN / TN, SEMROWS);
    rsum_inv<<<SYNROWS / 256, 256>>>(part2, inv2, SSEM / TN, SYNROWS);

    // ---- output: O[q,h] = (E[q,s] Vt[h,s]) * inv_rowsum[q], batched z=4 ----
    gemm_fp16<3, float, false><<<dim3(HID/TN, SSEM/TM, BATCH), 256, SMEM_GEMM>>>(
        p1, v1t, nullptr, nullptr, nullptr, o1, nullptr,
        HID, SSYN, SYNROWS,
        (long long)SSEM*SSYN, (long long)SSYN, (long long)SSEM*HID, 1.0f,
        nullptr, 0, inv1, (long long)SSEM);
    gemm_fp16<3, float, false><<<dim3(HID/TN, SSYN/TM, BATCH), 256, SMEM_GEMM>>>(
        p2, v2t, nullptr, nullptr, nullptr, o2, nullptr,
        HID, SSEM, SEMROWS,
        (long long)SSYN*SSEM, (long long)SSEM, (long long)SSYN*HID, 1.0f,
        nullptr, 0, inv2, (long long)SSYN);
}

// round 11
// speedup vs baseline: 1.1513x; 1.0533x over previous
#include <cuda_runtime.h>
#include <cuda_fp16.h>
#include <mma.h>
#include <math.h>
#include <stdint.h>

using namespace nvcuda;

// ---------------- problem constants ----------------
#define HID    768
#define BATCH  4
#define SSYN   4096
#define SSEM   2048
#define SEMROWS 8192     // BATCH*SSEM
#define SYNROWS 16384    // BATCH*SSYN

// ---------------- scratch (device globals; no allocations allowed) --------
__device__ __half g_semh[SEMROWS*HID];
__device__ __half g_synh[SYNROWS*HID];
__device__ __half g_wt[6*HID*HID];        // transposed weights [out,in] -> [N,K]
__device__ __half g_q1[SEMROWS*HID];
__device__ __half g_k1[SYNROWS*HID];
__device__ __half g_q2[SYNROWS*HID];
__device__ __half g_k2[SEMROWS*HID];
__device__ __half g_v1t[HID*SYNROWS];     // V1^T [768, 16384]
__device__ __half g_v2t[HID*SEMROWS];     // V2^T [768, 8192]
__device__ __half g_p1[(long long)BATCH*SSEM*SSYN];   // fp16 E = exp(scores)
__device__ __half g_p2[(long long)BATCH*SSYN*SSEM];
__device__ float  g_part1[32 * SEMROWS];  // per-n-tile row partial sums
__device__ float  g_part2[16 * SYNROWS];
__device__ float  g_inv1[SEMROWS];        // 1 / rowsum
__device__ float  g_inv2[SYNROWS];

struct H4 { __half2 a, b; };

// ---- fp16 wmma GEMM, 128x128x64 tile, 2-stage cp.async double buffer ----
// Multi-GEMM: several independent sub-GEMMs flattened into one 1D grid.
// Each sub: C = f(A @ B^T); A [M,K] row-major, B [N,K] (stride ldb), C ldc=N.
// BIASMODE: 1=col bias (fp16 out), 2=row bias (fp16 out),
//           3=row-scale (fp32 out), 4=exp-out fp16 + row partial sums
constexpr int TM = 128, TN = 128, TK = 64;
constexpr int KP = 72;                        // padded halfs per tile row (144B)
constexpr int TILE_H = 128 * KP;
constexpr int STAGE_H = 2 * TILE_H;
constexpr int STAGE_BYTES = STAGE_H * 2;      // 36864
constexpr int SMEM_GEMM = 2 * STAGE_BYTES + 512;  // 74240 B

struct GArg {
    const __half* A;
    const __half* B;
    const float*  bias;
    void*         C;
    int  N, K, ldb;
    long long sA, sB, sC;
    float scale;
    float* part;          // mode 4
    int    Mb;            // mode 4: rows per batch
    const float* rowscale; // mode 3
    long long sR;
    int nx, ny, nz;       // sub-grid dims
};
template<int NG> struct GPack { GArg g[NG]; int cum[NG]; };

__device__ __forceinline__ void cpa16(__half* dst, const __half* src) {
    unsigned d = (unsigned)__cvta_generic_to_shared(dst);
    asm volatile("cp.async.cg.shared.global [%0], [%1], 16;" :: "r"(d), "l"(src));
}

template<int BIASMODE, typename CT, int NG>
__global__ __launch_bounds__(256, 2)
void gemm_multi(GPack<NG> P)
{
    extern __shared__ __align__(16) __half sm[];
    float* biassm = (float*)((char*)sm + 2 * STAGE_BYTES);

    int flat = blockIdx.x, gi = 0;
    #pragma unroll
    for (int i = 0; i + 1 < NG; i++) if (flat >= P.cum[i]) gi = i + 1;
    const GArg& g = P.g[gi];
    int r = flat - (gi ? P.cum[gi - 1] : 0);
    const int bx = r % g.nx; r /= g.nx;
    const int by = r % g.ny;
    const long long z = r / g.ny;

    const int tid = threadIdx.x;
    const int wid = tid >> 5;
    const int wm  = wid & 1;               // warp row 0..1 (64 rows)
    const int wn  = wid >> 1;              // warp col 0..3 (32 cols)

    const int N = g.N, K = g.K, ldb = g.ldb;
    const float scale = g.scale;
    const int n0 = bx * TN;
    const long long row0 = (long long)by * TM;
    const __half* Ab = g.A + z * g.sA + row0 * K;
    const __half* Bb = g.B + z * g.sB + (long long)n0 * ldb;
    CT* Cb = (CT*)g.C + z * g.sC;

    if (BIASMODE == 1 && tid < TN) biassm[tid] = g.bias[n0 + tid];
    if (BIASMODE == 2 && tid < TM) biassm[tid] = g.bias[row0 + tid];
    if (BIASMODE == 3 && tid < TM) biassm[tid] = g.rowscale[z * g.sR + row0 + tid];

    wmma::fragment<wmma::matrix_a, 16, 16, 16, __half, wmma::row_major> af[4];
    wmma::fragment<wmma::matrix_b, 16, 16, 16, __half, wmma::col_major> bf[2];
    wmma::fragment<wmma::accumulator, 16, 16, 16, float> cf[4][2];
    #pragma unroll
    for (int i = 0; i < 4; i++)
        #pragma unroll
        for (int j = 0; j < 2; j++)
            wmma::fill_fragment(cf[i][j], 0.0f);

    const int nt = K / TK;

    auto load_tiles = [&](int t, int stage) {
        const __half* Ag = Ab + (long long)t * TK;
        __half* da = sm + stage * STAGE_H;
        #pragma unroll
        for (int i = 0; i < 4; i++) {
            int idx = tid + (i << 8);
            int rr = idx >> 3, c = (idx & 7) << 3;
            cpa16(da + rr * KP + c, Ag + (long long)rr * K + c);
        }
        const __half* Bg = Bb + (long long)t * TK;
        __half* db = da + TILE_H;
        #pragma unroll
        for (int i = 0; i < 4; i++) {
            int idx = tid + (i << 8);
            int rr = idx >> 3, c = (idx & 7) << 3;
            cpa16(db + rr * KP + c, Bg + (long long)rr * ldb + c);
        }
    };

    load_tiles(0, 0);
    asm volatile("cp.async.commit_group;");

    for (int t = 0; t < nt; t++) {
        if (t + 1 < nt) load_tiles(t + 1, (t + 1) & 1);
        asm volatile("cp.async.commit_group;");
        if (t + 1 < nt)
            asm volatile("cp.async.wait_group 1;");
        else
            asm volatile("cp.async.wait_group 0;");
        __syncthreads();

        const __half* Ad = sm + (t & 1) * STAGE_H;
        const __half* Bd = Ad + TILE_H;
        #pragma unroll
        for (int kk = 0; kk < 4; kk++) {
            #pragma unroll
            for (int i = 0; i < 4; i++)
                wmma::load_matrix_sync(af[i], Ad + (wm * 64 + i * 16) * KP + kk * 16, KP);
            #pragma unroll
            for (int j = 0; j < 2; j++)
                wmma::load_matrix_sync(bf[j], Bd + (wn * 32 + j * 16) * KP + kk * 16, KP);
            #pragma unroll
            for (int i = 0; i < 4; i++)
                #pragma unroll
                for (int j = 0; j < 2; j++)
                    wmma::mma_sync(cf[i][j], af[i], bf[j], cf[i][j]);
        }
        __syncthreads();
    }

    // ---- epilogue: stage fp32 accumulators through smem ----
    float* Cs = (float*)sm;    // [128][136]
    #pragma unroll
    for (int i = 0; i < 4; i++)
        #pragma unroll
        for (int j = 0; j < 2; j++)
            wmma::store_matrix_sync(Cs + (wm * 64 + i * 16) * 136 + wn * 32 + j * 16,
                                    cf[i][j], 136, wmma::mem_row_major);
    __syncthreads();

    if (BIASMODE == 3) {
        // fp32 output with per-row scale
        #pragma unroll
        for (int i = 0; i < 16; i++) {
            int idx = tid + (i << 8);
            int rr = idx >> 5, c = (idx & 31) << 2;
            float4 v = *reinterpret_cast<const float4*>(Cs + rr * 136 + c);
            float rb = biassm[rr];
            v.x *= rb; v.y *= rb; v.z *= rb; v.w *= rb;
            *reinterpret_cast<float4*>((float*)Cb + (row0 + rr) * N + n0 + c) = v;
        }
    } else if (BIASMODE == 4) {
        // E = exp(score*scale) fp16 out + per-tile row partial sums
        #pragma unroll
        for (int i = 0; i < 8; i++) {
            int idx = tid + (i << 8);
            int rr = idx >> 4, c = (idx & 15) << 3;
            float4 v0 = *reinterpret_cast<const float4*>(Cs + rr * 136 + c);
            float4 v1 = *reinterpret_cast<const float4*>(Cs + rr * 136 + c + 4);
            v0.x = __expf(v0.x * scale); v0.y = __expf(v0.y * scale);
            v0.z = __expf(v0.z * scale); v0.w = __expf(v0.w * scale);
            v1.x = __expf(v1.x * scale); v1.y = __expf(v1.y * scale);
            v1.z = __expf(v1.z * scale); v1.w = __expf(v1.w * scale);
            *reinterpret_cast<float4*>(Cs + rr * 136 + c) = v0;
            *reinterpret_cast<float4*>(Cs + rr * 136 + c + 4) = v1;
            __half2 h0 = __floats2half2_rn(v0.x, v0.y);
            __half2 h1 = __floats2half2_rn(v0.z, v0.w);
            __half2 h2 = __floats2half2_rn(v1.x, v1.y);
            __half2 h3 = __floats2half2_rn(v1.z, v1.w);
            uint4 pk;
            pk.x = *(unsigned*)&h0; pk.y = *(unsigned*)&h1;
            pk.z = *(unsigned*)&h2; pk.w = *(unsigned*)&h3;
            *reinterpret_cast<uint4*>((__half*)Cb + (row0 + rr) * N + n0 + c) = pk;
        }
        __syncthreads();
        if (tid < TM) {
            const float* rp = Cs + tid * 136;
            float s = 0.0f;
            #pragma unroll
            for (int c4 = 0; c4 < 32; c4++) {
                float4 v = *reinterpret_cast<const float4*>(rp + (c4 << 2));
                s += v.x + v.y + v.z + v.w;
            }
            g.part[(long long)bx * ((long long)g.nz * g.Mb)
                   + z * g.Mb + row0 + tid] = s;
        }
    } else {
        // fp16 output, col (1) or row (2) bias
        #pragma unroll
        for (int i = 0; i < 8; i++) {
            int idx = tid + (i << 8);
            int rr = idx >> 4, c = (idx & 15) << 3;
            float4 v0 = *reinterpret_cast<const float4*>(Cs + rr * 136 + c);
            float4 v1 = *reinterpret_cast<const float4*>(Cs + rr * 136 + c + 4);
            if (BIASMODE == 1) {
                v0.x += biassm[c + 0]; v0.y += biassm[c + 1];
                v0.z += biassm[c + 2]; v0.w += biassm[c + 3];
                v1.x += biassm[c + 4]; v1.y += biassm[c + 5];
                v1.z += biassm[c + 6]; v1.w += biassm[c + 7];
            }
            if (BIASMODE == 2) {
                float rb = biassm[rr];
                v0.x += rb; v0.y += rb; v0.z += rb; v0.w += rb;
                v1.x += rb; v1.y += rb; v1.z += rb; v1.w += rb;
            }
            __half2 h0 = __floats2half2_rn(v0.x, v0.y);
            __half2 h1 = __floats2half2_rn(v0.z, v0.w);
            __half2 h2 = __floats2half2_rn(v1.x, v1.y);
            __half2 h3 = __floats2half2_rn(v1.z, v1.w);
            uint4 pk;
            pk.x = *(unsigned*)&h0; pk.y = *(unsigned*)&h1;
            pk.z = *(unsigned*)&h2; pk.w = *(unsigned*)&h3;
            *reinterpret_cast<uint4*>((__half*)Cb + (row0 + rr) * N + n0 + c) = pk;
        }
    }
}

// ---------------- rowsum reduce: inv[q] = 1 / sum_i part[i][q] ------------
__global__ __launch_bounds__(256)
void rsum_inv(const float* __restrict__ part, float* __restrict__ inv,
              int nparts, int rows)
{
    int q = blockIdx.x * 256 + threadIdx.x;
    if (q < rows) {
        float s = 0.0f;
        for (int i = 0; i < nparts; i++) s += part[(long long)i * rows + q];
        inv[q] = 1.0f / s;
    }
}

// ---------------- elementwise fp32 -> fp16 ----------------
__global__ __launch_bounds__(256)
void cvt_half(const float* __restrict__ in, __half* __restrict__ out, int n)
{
    int i = (blockIdx.x * 256 + threadIdx.x) * 4;
    if (i < n) {
        float4 v = *reinterpret_cast<const float4*>(in + i);
        H4 h; __half2* hp = (__half2*)&h;
        hp[0] = __floats2half2_rn(v.x, v.y);
        hp[1] = __floats2half2_rn(v.z, v.w);
        *reinterpret_cast<H4*>(out + i) = h;
    }
}

// -------- batched transpose fp32 -> fp16 (all 6 weights in one launch) ----
struct WSet { const float* in[6]; };
__global__ __launch_bounds__(256)
void transpose_h6(WSet ws, __half* __restrict__ out)
{
    __shared__ float ts[32][33];
    const int R = HID, C = HID;
    const float* in = ws.in[blockIdx.z];
    __half* o = out + (long long)blockIdx.z * HID * HID;
    int tx = threadIdx.x & 31, ty = threadIdx.x >> 5;
    int c0 = blockIdx.x * 32, r0 = blockIdx.y * 32;
    #pragma unroll
    for (int j = 0; j < 4; j++)
        ts[ty + j * 8][tx] = in[(long long)(r0 + ty + j * 8) * C + c0 + tx];
    __syncthreads();
    #pragma unroll
    for (int j = 0; j < 4; j++)
        o[(long long)(c0 + ty + j * 8) * R + r0 + tx] = __float2half_rn(ts[tx][ty + j * 8]);
}

// ---------------- launcher ----------------
extern "C" void kernel_launch(void* const* d_in, const int* in_sizes, int n_in,
                              void* d_out, int out_size)
{
    const float* syn = (const float*)d_in[0];
    const float* sem = (const float*)d_in[1];
    const float* Wq1 = (const float*)d_in[2];  const float* bq1 = (const float*)d_in[3];
    const float* Wk1 = (const float*)d_in[4];  const float* bk1 = (const float*)d_in[5];
    const float* Wv1 = (const float*)d_in[6];  const float* bv1 = (const float*)d_in[7];
    const float* Wq2 = (const float*)d_in[8];  const float* bq2 = (const float*)d_in[9];
    const float* Wk2 = (const float*)d_in[10]; const float* bk2 = (const float*)d_in[11];
    const float* Wv2 = (const float*)d_in[12]; const float* bv2 = (const float*)d_in[13];

    float* o1 = (float*)d_out;                      // [4,2048,768]
    float* o2 = o1 + (long long)SEMROWS * HID;      // [4,4096,768]

    __half *semh, *synh, *wt, *q1, *k1, *q2, *k2, *v1t, *v2t, *p1, *p2;
    float *part1, *part2, *inv1, *inv2;
    cudaGetSymbolAddress((void**)&semh, g_semh);
    cudaGetSymbolAddress((void**)&synh, g_synh);
    cudaGetSymbolAddress((void**)&wt, g_wt);
    cudaGetSymbolAddress((void**)&q1, g_q1);
    cudaGetSymbolAddress((void**)&k1, g_k1);
    cudaGetSymbolAddress((void**)&q2, g_q2);
    cudaGetSymbolAddress((void**)&k2, g_k2);
    cudaGetSymbolAddress((void**)&v1t, g_v1t);
    cudaGetSymbolAddress((void**)&v2t, g_v2t);
    cudaGetSymbolAddress((void**)&p1, g_p1);
    cudaGetSymbolAddress((void**)&p2, g_p2);
    cudaGetSymbolAddress((void**)&part1, g_part1);
    cudaGetSymbolAddress((void**)&part2, g_part2);
    cudaGetSymbolAddress((void**)&inv1, g_inv1);
    cudaGetSymbolAddress((void**)&inv2, g_inv2);

    cudaFuncSetAttribute(gemm_multi<1, __half, 4>,
                         cudaFuncAttributeMaxDynamicSharedMemorySize, SMEM_GEMM);
    cudaFuncSetAttribute(gemm_multi<2, __half, 2>,
                         cudaFuncAttributeMaxDynamicSharedMemorySize, SMEM_GEMM);
    cudaFuncSetAttribute(gemm_multi<4, __half, 2>,
                         cudaFuncAttributeMaxDynamicSharedMemorySize, SMEM_GEMM);
    cudaFuncSetAttribute(gemm_multi<3, float, 2>,
                         cudaFuncAttributeMaxDynamicSharedMemorySize, SMEM_GEMM);

    const float scale = 1.0f / sqrtf((float)HID);
    const long long WN = (long long)HID * HID;

    // ---- convert inputs; transpose+convert all weights ----
    cvt_half<<<SEMROWS * HID / 1024, 256>>>(sem, semh, SEMROWS * HID);
    cvt_half<<<SYNROWS * HID / 1024, 256>>>(syn, synh, SYNROWS * HID);
    WSet ws;
    ws.in[0] = Wq1; ws.in[1] = Wk1; ws.in[2] = Wv1;
    ws.in[3] = Wq2; ws.in[4] = Wk2; ws.in[5] = Wv2;
    transpose_h6<<<dim3(HID / 32, HID / 32, 6), 256>>>(ws, wt);

    auto mk = [&](const __half* A, const __half* B, const float* bias, void* C,
                  int N, int K, int ldb, long long sA, long long sB, long long sC,
                  float sc, float* part, int Mb, const float* rsc, long long sR,
                  int nx, int ny, int nz) {
        GArg a;
        a.A = A; a.B = B; a.bias = bias; a.C = C;
        a.N = N; a.K = K; a.ldb = ldb; a.sA = sA; a.sB = sB; a.sC = sC;
        a.scale = sc; a.part = part; a.Mb = Mb; a.rowscale = rsc; a.sR = sR;
        a.nx = nx; a.ny = ny; a.nz = nz;
        return a;
    };

    // ---- Q/K projections: 4 sub-GEMMs, one launch (2304 CTAs) ----
    {
        GPack<4> P;
        P.g[0] = mk(semh, wt + 0 * WN, bq1, q1, HID, HID, HID, 0, 0, 0, 1.0f,
                    nullptr, 0, nullptr, 0, HID/TN, SEMROWS/TM, 1);
        P.g[1] = mk(semh, wt + 4 * WN, bk2, k2, HID, HID, HID, 0, 0, 0, 1.0f,
                    nullptr, 0, nullptr, 0, HID/TN, SEMROWS/TM, 1);
        P.g[2] = mk(synh, wt + 1 * WN, bk1, k1, HID, HID, HID, 0, 0, 0, 1.0f,
                    nullptr, 0, nullptr, 0, HID/TN, SYNROWS/TM, 1);
        P.g[3] = mk(synh, wt + 3 * WN, bq2, q2, HID, HID, HID, 0, 0, 0, 1.0f,
                    nullptr, 0, nullptr, 0, HID/TN, SYNROWS/TM, 1);
        P.cum[0] = 384; P.cum[1] = 768; P.cum[2] = 1536; P.cum[3] = 2304;
        gemm_multi<1, __half, 4><<<2304, 256, SMEM_GEMM>>>(P);
    }

    // ---- V projections (transposed out): 2 subs, one launch (1152 CTAs) ----
    {
        GPack<2> P;
        P.g[0] = mk(wt + 2 * WN, synh, bv1, v1t, SYNROWS, HID, HID, 0, 0, 0, 1.0f,
                    nullptr, 0, nullptr, 0, SYNROWS/TN, HID/TM, 1);
        P.g[1] = mk(wt + 5 * WN, semh, bv2, v2t, SEMROWS, HID, HID, 0, 0, 0, 1.0f,
                    nullptr, 0, nullptr, 0, SEMROWS/TN, HID/TM, 1);
        P.cum[0] = 768; P.cum[1] = 1152;
        gemm_multi<2, __half, 2><<<1152, 256, SMEM_GEMM>>>(P);
    }

    // ---- scores+exp: 2 subs, one launch (2048 + 2048 = 4096 CTAs) ----
    {
        GPack<2> P;
        P.g[0] = mk(q1, k1, nullptr, p1, SSYN, HID, HID,
                    (long long)SSEM*HID, (long long)SSYN*HID, (long long)SSEM*SSYN,
                    scale, part1, SSEM, nullptr, 0, SSYN/TN, SSEM/TM, BATCH);
        P.g[1] = mk(q2, k2, nullptr, p2, SSEM, HID, HID,
                    (long long)SSYN*HID, (long long)SSEM*HID, (long long)SSYN*SSEM,
                    scale, part2, SSYN, nullptr, 0, SSEM/TN, SSYN/TM, BATCH);
        P.cum[0] = 2048; P.cum[1] = 4096;   // FIX: sub1 = 16*32*4 = 2048 CTAs
        gemm_multi<4, __half, 2><<<4096, 256, SMEM_GEMM>>>(P);
    }

    // ---- inverse row sums ----
    rsum_inv<<<SEMROWS / 256, 256>>>(part1, inv1, SSYN / TN, SEMROWS);
    rsum_inv<<<SYNROWS / 256, 256>>>(part2, inv2, SSEM / TN, SYNROWS);

    // ---- PV: 2 subs, one launch (1152 CTAs) ----
    {
        GPack<2> P;
        P.g[0] = mk(p1, v1t, nullptr, o1, HID, SSYN, SYNROWS,
                    (long long)SSEM*SSYN, (long long)SSYN, (long long)SSEM*HID,
                    1.0f, nullptr, 0, inv1, (long long)SSEM, HID/TN, SSEM/TM, BATCH);
        P.g[1] = mk(p2, v2t, nullptr, o2, HID, SSEM, SEMROWS,
                    (long long)SSYN*SSEM, (long long)SSEM, (long long)SSYN*HID,
                    1.0f, nullptr, 0, inv2, (long long)SSYN, HID/TN, SSYN/TM, BATCH);
        P.cum[0] = 384; P.cum[1] = 1152;
        gemm_multi<3, float, 2><<<1152, 256, SMEM_GEMM>>>(P);
    }
}

// round 12
// speedup vs baseline: 1.1647x; 1.0117x over previous
#include <cuda_runtime.h>
#include <cuda_fp16.h>
#include <mma.h>
#include <math.h>
#include <stdint.h>

using namespace nvcuda;

// ---------------- problem constants ----------------
#define HID    768
#define BATCH  4
#define SSYN   4096
#define SSEM   2048
#define SEMROWS 8192     // BATCH*SSEM
#define SYNROWS 16384    // BATCH*SSYN

// ---------------- scratch (device globals; no allocations allowed) --------
__device__ __half g_semh[SEMROWS*HID];
__device__ __half g_synh[SYNROWS*HID];
__device__ __half g_wt[6*HID*HID];        // transposed weights [out,in] -> [N,K]
__device__ __half g_q1[SEMROWS*HID];
__device__ __half g_k1[SYNROWS*HID];
__device__ __half g_q2[SYNROWS*HID];
__device__ __half g_k2[SEMROWS*HID];
__device__ __half g_v1t[HID*SYNROWS];     // V1^T [768, 16384]
__device__ __half g_v2t[HID*SEMROWS];     // V2^T [768, 8192]
__device__ __half g_p1[(long long)BATCH*SSEM*SSYN];   // fp16 E = exp(scores)
__device__ __half g_p2[(long long)BATCH*SSYN*SSEM];
__device__ float  g_part1[32 * SEMROWS];  // per-n-tile row partial sums
__device__ float  g_part2[16 * SYNROWS];
__device__ float  g_inv1[SEMROWS];        // 1 / rowsum
__device__ float  g_inv2[SYNROWS];

struct H4 { __half2 a, b; };

// ---- fp16 wmma GEMM, 128x128x64 tile, 2-stage cp.async double buffer ----
// Multi-GEMM: several independent sub-GEMMs flattened into one 1D grid.
// Each sub: C = f(A @ B^T); A [M,K] row-major, B [N,K] (stride ldb), C ldc=N.
constexpr int TM = 128, TN = 128, TK = 64;
constexpr int KP = 72;                        // padded halfs per tile row (144B)
constexpr int TILE_H = 128 * KP;
constexpr int STAGE_H = 2 * TILE_H;
constexpr int STAGE_BYTES = STAGE_H * 2;      // 36864
constexpr int SMEM_GEMM = 2 * STAGE_BYTES + 512;  // 74240 B

struct GArg {
    const __half* A;
    const __half* B;
    const float*  bias;
    void*         C;
    int  N, K, ldb;
    long long sA, sB, sC;
    float scale;
    float* part;           // mode 4
    int    Mb;             // mode 4: rows per batch
    const float* rowscale; // mode 3
    long long sR;
    int nx, ny, nz;        // sub-grid dims
    int mode;              // runtime: 1=col bias, 2=row bias (proj kernel only)
};
template<int NG> struct GPack { GArg g[NG]; int cum[NG]; };

__device__ __forceinline__ void cpa16(__half* dst, const __half* src) {
    unsigned d = (unsigned)__cvta_generic_to_shared(dst);
    asm volatile("cp.async.cg.shared.global [%0], [%1], 16;" :: "r"(d), "l"(src));
}

// ------------- shared mainloop (identical across kernels) ------------------
// Returns with accumulators filled; Cs staging done by caller.
#define GEMM_MAINLOOP()                                                          \
    wmma::fragment<wmma::matrix_a, 16, 16, 16, __half, wmma::row_major> af[4];   \
    wmma::fragment<wmma::matrix_b, 16, 16, 16, __half, wmma::col_major> bf[2];   \
    wmma::fragment<wmma::accumulator, 16, 16, 16, float> cf[4][2];               \
    _Pragma("unroll")                                                            \
    for (int i = 0; i < 4; i++)                                                  \
        _Pragma("unroll")                                                        \
        for (int j = 0; j < 2; j++)                                              \
            wmma::fill_fragment(cf[i][j], 0.0f);                                 \
    const int nt = K / TK;                                                       \
    auto load_tiles = [&](int t, int stage) {                                    \
        const __half* Ag = Ab + (long long)t * TK;                               \
        __half* da = sm + stage * STAGE_H;                                       \
        _Pragma("unroll")                                                        \
        for (int i = 0; i < 4; i++) {                                            \
            int idx = tid + (i << 8);                                            \
            int rr = idx >> 3, c = (idx & 7) << 3;                               \
            cpa16(da + rr * KP + c, Ag + (long long)rr * K + c);                 \
        }                                                                        \
        const __half* Bg = Bb + (long long)t * TK;                               \
        __half* db = da + TILE_H;                                                \
        _Pragma("unroll")                                                        \
        for (int i = 0; i < 4; i++) {                                            \
            int idx = tid + (i << 8);                                            \
            int rr = idx >> 3, c = (idx & 7) << 3;                               \
            cpa16(db + rr * KP + c, Bg + (long long)rr * ldb + c);               \
        }                                                                        \
    };                                                                           \
    load_tiles(0, 0);                                                            \
    asm volatile("cp.async.commit_group;");                                      \
    for (int t = 0; t < nt; t++) {                                               \
        if (t + 1 < nt) load_tiles(t + 1, (t + 1) & 1);                          \
        asm volatile("cp.async.commit_group;");                                  \
        if (t + 1 < nt)                                                          \
            asm volatile("cp.async.wait_group 1;");                              \
        else                                                                     \
            asm volatile("cp.async.wait_group 0;");                              \
        __syncthreads();                                                         \
        const __half* Ad = sm + (t & 1) * STAGE_H;                               \
        const __half* Bd = Ad + TILE_H;                                          \
        _Pragma("unroll")                                                        \
        for (int kk = 0; kk < 4; kk++) {                                         \
            _Pragma("unroll")                                                    \
            for (int i = 0; i < 4; i++)                                          \
                wmma::load_matrix_sync(af[i], Ad + (wm * 64 + i * 16) * KP + kk * 16, KP); \
            _Pragma("unroll")                                                    \
            for (int j = 0; j < 2; j++)                                          \
                wmma::load_matrix_sync(bf[j], Bd + (wn * 32 + j * 16) * KP + kk * 16, KP); \
            _Pragma("unroll")                                                    \
            for (int i = 0; i < 4; i++)                                          \
                _Pragma("unroll")                                                \
                for (int j = 0; j < 2; j++)                                      \
                    wmma::mma_sync(cf[i][j], af[i], bf[j], cf[i][j]);            \
        }                                                                        \
        __syncthreads();                                                         \
    }                                                                            \
    float* Cs = (float*)sm;                                                      \
    _Pragma("unroll")                                                            \
    for (int i = 0; i < 4; i++)                                                  \
        _Pragma("unroll")                                                        \
        for (int j = 0; j < 2; j++)                                              \
            wmma::store_matrix_sync(Cs + (wm * 64 + i * 16) * 136 + wn * 32 + j * 16, \
                                    cf[i][j], 136, wmma::mem_row_major);         \
    __syncthreads();

#define GEMM_PREAMBLE(NG)                                                        \
    extern __shared__ __align__(16) __half sm[];                                 \
    float* biassm = (float*)((char*)sm + 2 * STAGE_BYTES);                       \
    int flat = blockIdx.x, gi = 0;                                               \
    _Pragma("unroll")                                                            \
    for (int i = 0; i + 1 < NG; i++) if (flat >= P.cum[i]) gi = i + 1;           \
    const GArg& g = P.g[gi];                                                     \
    int r = flat - (gi ? P.cum[gi - 1] : 0);                                     \
    const int bx = r % g.nx; r /= g.nx;                                          \
    const int by = r % g.ny;                                                     \
    const long long z = r / g.ny;                                                \
    const int tid = threadIdx.x;                                                 \
    const int wid = tid >> 5;                                                    \
    const int wm  = wid & 1;                                                     \
    const int wn  = wid >> 1;                                                    \
    const int N = g.N, K = g.K, ldb = g.ldb;                                     \
    const float scale = g.scale;                                                 \
    const int n0 = bx * TN;                                                      \
    const long long row0 = (long long)by * TM;                                   \
    const __half* Ab = g.A + z * g.sA + row0 * K;                                \
    const __half* Bb = g.B + z * g.sB + (long long)n0 * ldb;

// ---- projections: fp16 out, runtime col(1)/row(2) bias ----
template<int NG>
__global__ __launch_bounds__(256, 2)
void gemm_proj(GPack<NG> P)
{
    GEMM_PREAMBLE(NG)
    __half* Cb = (__half*)g.C + z * g.sC;
    const int mode = g.mode;
    if (mode == 1) { if (tid < TN) biassm[tid] = g.bias[n0 + tid]; }
    else           { if (tid < TM) biassm[tid] = g.bias[row0 + tid]; }
    GEMM_MAINLOOP()

    #pragma unroll
    for (int i = 0; i < 8; i++) {
        int idx = tid + (i << 8);
        int rr = idx >> 4, c = (idx & 15) << 3;
        float4 v0 = *reinterpret_cast<const float4*>(Cs + rr * 136 + c);
        float4 v1 = *reinterpret_cast<const float4*>(Cs + rr * 136 + c + 4);
        if (mode == 1) {
            v0.x += biassm[c + 0]; v0.y += biassm[c + 1];
            v0.z += biassm[c + 2]; v0.w += biassm[c + 3];
            v1.x += biassm[c + 4]; v1.y += biassm[c + 5];
            v1.z += biassm[c + 6]; v1.w += biassm[c + 7];
        } else {
            float rb = biassm[rr];
            v0.x += rb; v0.y += rb; v0.z += rb; v0.w += rb;
            v1.x += rb; v1.y += rb; v1.z += rb; v1.w += rb;
        }
        __half2 h0 = __floats2half2_rn(v0.x, v0.y);
        __half2 h1 = __floats2half2_rn(v0.z, v0.w);
        __half2 h2 = __floats2half2_rn(v1.x, v1.y);
        __half2 h3 = __floats2half2_rn(v1.z, v1.w);
        uint4 pk;
        pk.x = *(unsigned*)&h0; pk.y = *(unsigned*)&h1;
        pk.z = *(unsigned*)&h2; pk.w = *(unsigned*)&h3;
        *reinterpret_cast<uint4*>(Cb + (row0 + rr) * N + n0 + c) = pk;
    }
}

// ---- scores: E = exp(score*scale) fp16 out + per-tile row partial sums ----
template<int NG>
__global__ __launch_bounds__(256, 2)
void gemm_exp(GPack<NG> P)
{
    GEMM_PREAMBLE(NG)
    __half* Cb = (__half*)g.C + z * g.sC;
    GEMM_MAINLOOP()

    #pragma unroll
    for (int i = 0; i < 8; i++) {
        int idx = tid + (i << 8);
        int rr = idx >> 4, c = (idx & 15) << 3;
        float4 v0 = *reinterpret_cast<const float4*>(Cs + rr * 136 + c);
        float4 v1 = *reinterpret_cast<const float4*>(Cs + rr * 136 + c + 4);
        v0.x = __expf(v0.x * scale); v0.y = __expf(v0.y * scale);
        v0.z = __expf(v0.z * scale); v0.w = __expf(v0.w * scale);
        v1.x = __expf(v1.x * scale); v1.y = __expf(v1.y * scale);
        v1.z = __expf(v1.z * scale); v1.w = __expf(v1.w * scale);
        *reinterpret_cast<float4*>(Cs + rr * 136 + c) = v0;
        *reinterpret_cast<float4*>(Cs + rr * 136 + c + 4) = v1;
        __half2 h0 = __floats2half2_rn(v0.x, v0.y);
        __half2 h1 = __floats2half2_rn(v0.z, v0.w);
        __half2 h2 = __floats2half2_rn(v1.x, v1.y);
        __half2 h3 = __floats2half2_rn(v1.z, v1.w);
        uint4 pk;
        pk.x = *(unsigned*)&h0; pk.y = *(unsigned*)&h1;
        pk.z = *(unsigned*)&h2; pk.w = *(unsigned*)&h3;
        *reinterpret_cast<uint4*>(Cb + (row0 + rr) * N + n0 + c) = pk;
    }
    __syncthreads();
    if (tid < TM) {
        const float* rp = Cs + tid * 136;
        float s = 0.0f;
        #pragma unroll
        for (int c4 = 0; c4 < 32; c4++) {
            float4 v = *reinterpret_cast<const float4*>(rp + (c4 << 2));
            s += v.x + v.y + v.z + v.w;
        }
        g.part[(long long)bx * ((long long)g.nz * g.Mb) + z * g.Mb + row0 + tid] = s;
    }
}

// ---- PV: fp32 out scaled by per-row 1/rowsum ----
template<int NG>
__global__ __launch_bounds__(256, 2)
void gemm_pv(GPack<NG> P)
{
    GEMM_PREAMBLE(NG)
    float* Cb = (float*)g.C + z * g.sC;
    if (tid < TM) biassm[tid] = g.rowscale[z * g.sR + row0 + tid];
    GEMM_MAINLOOP()

    #pragma unroll
    for (int i = 0; i < 16; i++) {
        int idx = tid + (i << 8);
        int rr = idx >> 5, c = (idx & 31) << 2;
        float4 v = *reinterpret_cast<const float4*>(Cs + rr * 136 + c);
        float rb = biassm[rr];
        v.x *= rb; v.y *= rb; v.z *= rb; v.w *= rb;
        *reinterpret_cast<float4*>(Cb + (row0 + rr) * N + n0 + c) = v;
    }
}

// ---------------- combined rowsum reduce for both attention dirs ----------
__global__ __launch_bounds__(256)
void rsum_inv2(const float* __restrict__ part1, float* __restrict__ inv1,
               const float* __restrict__ part2, float* __restrict__ inv2)
{
    int q = blockIdx.x * 256 + threadIdx.x;
    if (q < SEMROWS) {
        float s = 0.0f;
        #pragma unroll 4
        for (int i = 0; i < 32; i++) s += part1[(long long)i * SEMROWS + q];
        inv1[q] = 1.0f / s;
    } else {
        int q2 = q - SEMROWS;
        float s = 0.0f;
        #pragma unroll 4
        for (int i = 0; i < 16; i++) s += part2[(long long)i * SYNROWS + q2];
        inv2[q2] = 1.0f / s;
    }
}

// ---------------- combined fp32 -> fp16 conversion for both inputs --------
__global__ __launch_bounds__(256)
void cvt_both(const float* __restrict__ in1, __half* __restrict__ out1, int n1,
              const float* __restrict__ in2, __half* __restrict__ out2)
{
    int i = (blockIdx.x * 256 + threadIdx.x) * 4;
    const float* in;
    __half* out;
    if (i < n1) { in = in1; out = out1; }
    else        { in = in2 - n1; out = out2 - n1; }
    float4 v = *reinterpret_cast<const float4*>(in + i);
    H4 h; __half2* hp = (__half2*)&h;
    hp[0] = __floats2half2_rn(v.x, v.y);
    hp[1] = __floats2half2_rn(v.z, v.w);
    *reinterpret_cast<H4*>(out + i) = h;
}

// -------- batched transpose fp32 -> fp16 (all 6 weights in one launch) ----
struct WSet { const float* in[6]; };
__global__ __launch_bounds__(256)
void transpose_h6(WSet ws, __half* __restrict__ out)
{
    __shared__ float ts[32][33];
    const int R = HID, C = HID;
    const float* in = ws.in[blockIdx.z];
    __half* o = out + (long long)blockIdx.z * HID * HID;
    int tx = threadIdx.x & 31, ty = threadIdx.x >> 5;
    int c0 = blockIdx.x * 32, r0 = blockIdx.y * 32;
    #pragma unroll
    for (int j = 0; j < 4; j++)
        ts[ty + j * 8][tx] = in[(long long)(r0 + ty + j * 8) * C + c0 + tx];
    __syncthreads();
    #pragma unroll
    for (int j = 0; j < 4; j++)
        o[(long long)(c0 + ty + j * 8) * R + r0 + tx] = __float2half_rn(ts[tx][ty + j * 8]);
}

// ---------------- launcher ----------------
extern "C" void kernel_launch(void* const* d_in, const int* in_sizes, int n_in,
                              void* d_out, int out_size)
{
    const float* syn = (const float*)d_in[0];
    const float* sem = (const float*)d_in[1];
    const float* Wq1 = (const float*)d_in[2];  const float* bq1 = (const float*)d_in[3];
    const float* Wk1 = (const float*)d_in[4];  const float* bk1 = (const float*)d_in[5];
    const float* Wv1 = (const float*)d_in[6];  const float* bv1 = (const float*)d_in[7];
    const float* Wq2 = (const float*)d_in[8];  const float* bq2 = (const float*)d_in[9];
    const float* Wk2 = (const float*)d_in[10]; const float* bk2 = (const float*)d_in[11];
    const float* Wv2 = (const float*)d_in[12]; const float* bv2 = (const float*)d_in[13];

    float* o1 = (float*)d_out;                      // [4,2048,768]
    float* o2 = o1 + (long long)SEMROWS * HID;      // [4,4096,768]

    __half *semh, *synh, *wt, *q1, *k1, *q2, *k2, *v1t, *v2t, *p1, *p2;
    float *part1, *part2, *inv1, *inv2;
    cudaGetSymbolAddress((void**)&semh, g_semh);
    cudaGetSymbolAddress((void**)&synh, g_synh);
    cudaGetSymbolAddress((void**)&wt, g_wt);
    cudaGetSymbolAddress((void**)&q1, g_q1);
    cudaGetSymbolAddress((void**)&k1, g_k1);
    cudaGetSymbolAddress((void**)&q2, g_q2);
    cudaGetSymbolAddress((void**)&k2, g_k2);
    cudaGetSymbolAddress((void**)&v1t, g_v1t);
    cudaGetSymbolAddress((void**)&v2t, g_v2t);
    cudaGetSymbolAddress((void**)&p1, g_p1);
    cudaGetSymbolAddress((void**)&p2, g_p2);
    cudaGetSymbolAddress((void**)&part1, g_part1);
    cudaGetSymbolAddress((void**)&part2, g_part2);
    cudaGetSymbolAddress((void**)&inv1, g_inv1);
    cudaGetSymbolAddress((void**)&inv2, g_inv2);

    cudaFuncSetAttribute(gemm_proj<6>,
                         cudaFuncAttributeMaxDynamicSharedMemorySize, SMEM_GEMM);
    cudaFuncSetAttribute(gemm_exp<2>,
                         cudaFuncAttributeMaxDynamicSharedMemorySize, SMEM_GEMM);
    cudaFuncSetAttribute(gemm_pv<2>,
                         cudaFuncAttributeMaxDynamicSharedMemorySize, SMEM_GEMM);

    const float scale = 1.0f / sqrtf((float)HID);
    const long long WN = (long long)HID * HID;

    // ---- convert both inputs in one launch; transpose all weights ----
    cvt_both<<<(SEMROWS + SYNROWS) * HID / 1024, 256>>>(
        sem, semh, SEMROWS * HID, syn, synh);
    WSet ws;
    ws.in[0] = Wq1; ws.in[1] = Wk1; ws.in[2] = Wv1;
    ws.in[3] = Wq2; ws.in[4] = Wk2; ws.in[5] = Wv2;
    transpose_h6<<<dim3(HID / 32, HID / 32, 6), 256>>>(ws, wt);

    auto mk = [&](const __half* A, const __half* B, const float* bias, void* C,
                  int N, int K, int ldb, long long sA, long long sB, long long sC,
                  float sc, float* part, int Mb, const float* rsc, long long sR,
                  int nx, int ny, int nz, int mode) {
        GArg a;
        a.A = A; a.B = B; a.bias = bias; a.C = C;
        a.N = N; a.K = K; a.ldb = ldb; a.sA = sA; a.sB = sB; a.sC = sC;
        a.scale = sc; a.part = part; a.Mb = Mb; a.rowscale = rsc; a.sR = sR;
        a.nx = nx; a.ny = ny; a.nz = nz; a.mode = mode;
        return a;
    };

    // ---- ALL 6 projections in one launch (3456 CTAs) ----
    {
        GPack<6> P;
        P.g[0] = mk(semh, wt + 0 * WN, bq1, q1, HID, HID, HID, 0, 0, 0, 1.0f,
                    nullptr, 0, nullptr, 0, HID/TN, SEMROWS/TM, 1, 1);
        P.g[1] = mk(semh, wt + 4 * WN, bk2, k2, HID, HID, HID, 0, 0, 0, 1.0f,
                    nullptr, 0, nullptr, 0, HID/TN, SEMROWS/TM, 1, 1);
        P.g[2] = mk(synh, wt + 1 * WN, bk1, k1, HID, HID, HID, 0, 0, 0, 1.0f,
                    nullptr, 0, nullptr, 0, HID/TN, SYNROWS/TM, 1, 1);
        P.g[3] = mk(synh, wt + 3 * WN, bq2, q2, HID, HID, HID, 0, 0, 0, 1.0f,
                    nullptr, 0, nullptr, 0, HID/TN, SYNROWS/TM, 1, 1);
        P.g[4] = mk(wt + 2 * WN, synh, bv1, v1t, SYNROWS, HID, HID, 0, 0, 0, 1.0f,
                    nullptr, 0, nullptr, 0, SYNROWS/TN, HID/TM, 1, 2);
        P.g[5] = mk(wt + 5 * WN, semh, bv2, v2t, SEMROWS, HID, HID, 0, 0, 0, 1.0f,
                    nullptr, 0, nullptr, 0, SEMROWS/TN, HID/TM, 1, 2);
        // sub sizes: 384, 384, 768, 768, 768, 384
        P.cum[0] = 384; P.cum[1] = 768; P.cum[2] = 1536;
        P.cum[3] = 2304; P.cum[4] = 3072; P.cum[5] = 3456;
        gemm_proj<6><<<3456, 256, SMEM_GEMM>>>(P);
    }

    // ---- scores+exp: 2 subs, one launch (2048 + 2048 = 4096 CTAs) ----
    {
        GPack<2> P;
        P.g[0] = mk(q1, k1, nullptr, p1, SSYN, HID, HID,
                    (long long)SSEM*HID, (long long)SSYN*HID, (long long)SSEM*SSYN,
                    scale, part1, SSEM, nullptr, 0, SSYN/TN, SSEM/TM, BATCH, 0);
        P.g[1] = mk(q2, k2, nullptr, p2, SSEM, HID, HID,
                    (long long)SSYN*HID, (long long)SSEM*HID, (long long)SSYN*SSEM,
                    scale, part2, SSYN, nullptr, 0, SSEM/TN, SSYN/TM, BATCH, 0);
        P.cum[0] = 2048; P.cum[1] = 4096;
        gemm_exp<2><<<4096, 256, SMEM_GEMM>>>(P);
    }

    // ---- both inverse row-sum sets in one launch ----
    rsum_inv2<<<(SEMROWS + SYNROWS) / 256, 256>>>(part1, inv1, part2, inv2);

    // ---- PV: 2 subs, one launch (1152 CTAs) ----
    {
        GPack<2> P;
        P.g[0] = mk(p1, v1t, nullptr, o1, HID, SSYN, SYNROWS,
                    (long long)SSEM*SSYN, (long long)SSYN, (long long)SSEM*HID,
                    1.0f, nullptr, 0, inv1, (long long)SSEM, HID/TN, SSEM/TM, BATCH, 0);
        P.g[1] = mk(p2, v2t, nullptr, o2, HID, SSEM, SEMROWS,
                    (long long)SSYN*SSEM, (long long)SSEM, (long long)SSYN*HID,
                    1.0f, nullptr, 0, inv2, (long long)SSYN, HID/TN, SSYN/TM, BATCH, 0);
        P.cum[0] = 384; P.cum[1] = 1152;
        gemm_pv<2><<<1152, 256, SMEM_GEMM>>>(P);
    }
}

// round 13
// speedup vs baseline: 1.1827x; 1.0154x over previous
#include <cuda_runtime.h>
#include <cuda_fp16.h>
#include <mma.h>
#include <math.h>
#include <stdint.h>

using namespace nvcuda;

// ---------------- problem constants ----------------
#define HID    768
#define BATCH  4
#define SSYN   4096
#define SSEM   2048
#define SEMROWS 8192     // BATCH*SSEM
#define SYNROWS 16384    // BATCH*SSYN

// ---------------- scratch (device globals; no allocations allowed) --------
__device__ __half g_semh[SEMROWS*HID];
__device__ __half g_synh[SYNROWS*HID];
__device__ __half g_wt[6*HID*HID];        // transposed weights [out,in] -> [N,K]
__device__ __half g_q1[SEMROWS*HID];
__device__ __half g_k1[SYNROWS*HID];
__device__ __half g_q2[SYNROWS*HID];
__device__ __half g_k2[SEMROWS*HID];
__device__ __half g_v1t[HID*SYNROWS];     // V1^T [768, 16384]
__device__ __half g_v2t[HID*SEMROWS];     // V2^T [768, 8192]
__device__ __half g_p1[(long long)BATCH*SSEM*SSYN];   // fp16 E = exp(scores)
__device__ __half g_p2[(long long)BATCH*SSYN*SSEM];
__device__ float  g_part1[32 * SEMROWS];  // per-n-tile row partial sums
__device__ float  g_part2[16 * SYNROWS];
__device__ float  g_inv1[SEMROWS];        // 1 / rowsum
__device__ float  g_inv2[SYNROWS];

struct H4 { __half2 a, b; };

// ---- fp16 wmma GEMM, 128x128x64 tile, 2-stage cp.async double buffer ----
constexpr int TM = 128, TN = 128, TK = 64;
constexpr int KP = 72;                        // padded halfs per tile row (144B)
constexpr int TILE_H = 128 * KP;
constexpr int STAGE_H = 2 * TILE_H;
constexpr int STAGE_BYTES = STAGE_H * 2;      // 36864
constexpr int SMEM_GEMM = 2 * STAGE_BYTES + 512;  // 74240 B

struct GArg {
    const __half* A;
    const __half* B;
    const float*  bias;
    void*         C;
    int  N, K, ldb;
    long long sA, sB, sC;
    float scale;
    float* part;           // exp kernel
    int    Mb;             // exp kernel: rows per batch
    const float* rowscale; // pv kernel
    long long sR;
    int nx, ny, nz;        // sub-grid dims
    int mode;              // proj kernel: 1=col bias, 2=row bias
};
template<int NG> struct GPack { GArg g[NG]; int cum[NG]; };

__device__ __forceinline__ void cpa16(__half* dst, const __half* src) {
    unsigned d = (unsigned)__cvta_generic_to_shared(dst);
    asm volatile("cp.async.cg.shared.global [%0], [%1], 16;" :: "r"(d), "l"(src));
}

#define GEMM_MAINLOOP()                                                          \
    wmma::fragment<wmma::matrix_a, 16, 16, 16, __half, wmma::row_major> af[4];   \
    wmma::fragment<wmma::matrix_b, 16, 16, 16, __half, wmma::col_major> bf[2];   \
    wmma::fragment<wmma::accumulator, 16, 16, 16, float> cf[4][2];               \
    _Pragma("unroll")                                                            \
    for (int i = 0; i < 4; i++)                                                  \
        _Pragma("unroll")                                                        \
        for (int j = 0; j < 2; j++)                                              \
            wmma::fill_fragment(cf[i][j], 0.0f);                                 \
    const int nt = K / TK;                                                       \
    auto load_tiles = [&](int t, int stage) {                                    \
        const __half* Ag = Ab + (long long)t * TK;                               \
        __half* da = sm + stage * STAGE_H;                                       \
        _Pragma("unroll")                                                        \
        for (int i = 0; i < 4; i++) {                                            \
            int idx = tid + (i << 8);                                            \
            int rr = idx >> 3, c = (idx & 7) << 3;                               \
            cpa16(da + rr * KP + c, Ag + (long long)rr * K + c);                 \
        }                                                                        \
        const __half* Bg = Bb + (long long)t * TK;                               \
        __half* db = da + TILE_H;                                                \
        _Pragma("unroll")                                                        \
        for (int i = 0; i < 4; i++) {                                            \
            int idx = tid + (i << 8);                                            \
            int rr = idx >> 3, c = (idx & 7) << 3;                               \
            cpa16(db + rr * KP + c, Bg + (long long)rr * ldb + c);               \
        }                                                                        \
    };                                                                           \
    load_tiles(0, 0);                                                            \
    asm volatile("cp.async.commit_group;");                                      \
    for (int t = 0; t < nt; t++) {                                               \
        if (t + 1 < nt) load_tiles(t + 1, (t + 1) & 1);                          \
        asm volatile("cp.async.commit_group;");                                  \
        if (t + 1 < nt)                                                          \
            asm volatile("cp.async.wait_group 1;");                              \
        else                                                                     \
            asm volatile("cp.async.wait_group 0;");                              \
        __syncthreads();                                                         \
        const __half* Ad = sm + (t & 1) * STAGE_H;                               \
        const __half* Bd = Ad + TILE_H;                                          \
        _Pragma("unroll")                                                        \
        for (int kk = 0; kk < 4; kk++) {                                         \
            _Pragma("unroll")                                                    \
            for (int i = 0; i < 4; i++)                                          \
                wmma::load_matrix_sync(af[i], Ad + (wm * 64 + i * 16) * KP + kk * 16, KP); \
            _Pragma("unroll")                                                    \
            for (int j = 0; j < 2; j++)                                          \
                wmma::load_matrix_sync(bf[j], Bd + (wn * 32 + j * 16) * KP + kk * 16, KP); \
            _Pragma("unroll")                                                    \
            for (int i = 0; i < 4; i++)                                          \
                _Pragma("unroll")                                                \
                for (int j = 0; j < 2; j++)                                      \
                    wmma::mma_sync(cf[i][j], af[i], bf[j], cf[i][j]);            \
        }                                                                        \
        __syncthreads();                                                         \
    }                                                                            \
    float* Cs = (float*)sm;                                                      \
    _Pragma("unroll")                                                            \
    for (int i = 0; i < 4; i++)                                                  \
        _Pragma("unroll")                                                        \
        for (int j = 0; j < 2; j++)                                              \
            wmma::store_matrix_sync(Cs + (wm * 64 + i * 16) * 136 + wn * 32 + j * 16, \
                                    cf[i][j], 136, wmma::mem_row_major);         \
    __syncthreads();

#define GEMM_PREAMBLE(NG)                                                        \
    extern __shared__ __align__(16) __half sm[];                                 \
    float* biassm = (float*)((char*)sm + 2 * STAGE_BYTES);                       \
    int flat = blockIdx.x, gi = 0;                                               \
    _Pragma("unroll")                                                            \
    for (int i = 0; i + 1 < NG; i++) if (flat >= P.cum[i]) gi = i + 1;           \
    const GArg& g = P.g[gi];                                                     \
    int r = flat - (gi ? P.cum[gi - 1] : 0);                                     \
    const int bx = r % g.nx; r /= g.nx;                                          \
    const int by = r % g.ny;                                                     \
    const long long z = r / g.ny;                                                \
    const int tid = threadIdx.x;                                                 \
    const int wid = tid >> 5;                                                    \
    const int wm  = wid & 1;                                                     \
    const int wn  = wid >> 1;                                                    \
    const int N = g.N, K = g.K, ldb = g.ldb;                                     \
    const float scale = g.scale;                                                 \
    const int n0 = bx * TN;                                                      \
    const long long row0 = (long long)by * TM;                                   \
    const __half* Ab = g.A + z * g.sA + row0 * K;                                \
    const __half* Bb = g.B + z * g.sB + (long long)n0 * ldb;

// ---- projections: fp16 out, runtime col(1)/row(2) bias ----
template<int NG>
__global__ __launch_bounds__(256, 2)
void gemm_proj(GPack<NG> P)
{
    GEMM_PREAMBLE(NG)
    __half* Cb = (__half*)g.C + z * g.sC;
    const int mode = g.mode;
    if (mode == 1) { if (tid < TN) biassm[tid] = g.bias[n0 + tid]; }
    else           { if (tid < TM) biassm[tid] = g.bias[row0 + tid]; }
    GEMM_MAINLOOP()

    #pragma unroll
    for (int i = 0; i < 8; i++) {
        int idx = tid + (i << 8);
        int rr = idx >> 4, c = (idx & 15) << 3;
        float4 v0 = *reinterpret_cast<const float4*>(Cs + rr * 136 + c);
        float4 v1 = *reinterpret_cast<const float4*>(Cs + rr * 136 + c + 4);
        if (mode == 1) {
            v0.x += biassm[c + 0]; v0.y += biassm[c + 1];
            v0.z += biassm[c + 2]; v0.w += biassm[c + 3];
            v1.x += biassm[c + 4]; v1.y += biassm[c + 5];
            v1.z += biassm[c + 6]; v1.w += biassm[c + 7];
        } else {
            float rb = biassm[rr];
            v0.x += rb; v0.y += rb; v0.z += rb; v0.w += rb;
            v1.x += rb; v1.y += rb; v1.z += rb; v1.w += rb;
        }
        __half2 h0 = __floats2half2_rn(v0.x, v0.y);
        __half2 h1 = __floats2half2_rn(v0.z, v0.w);
        __half2 h2 = __floats2half2_rn(v1.x, v1.y);
        __half2 h3 = __floats2half2_rn(v1.z, v1.w);
        uint4 pk;
        pk.x = *(unsigned*)&h0; pk.y = *(unsigned*)&h1;
        pk.z = *(unsigned*)&h2; pk.w = *(unsigned*)&h3;
        *reinterpret_cast<uint4*>(Cb + (row0 + rr) * N + n0 + c) = pk;
    }
}

// ---- scores: E = exp(score*scale) fp16 out; row sums via shfl (no Cs pass) ----
template<int NG>
__global__ __launch_bounds__(256, 2)
void gemm_exp(GPack<NG> P)
{
    GEMM_PREAMBLE(NG)
    __half* Cb = (__half*)g.C + z * g.sC;
    GEMM_MAINLOOP()

    // Each row rr's 128 columns live in one iteration i across 16 consecutive
    // lanes (idx = tid + 256*i, rr = idx>>4) -> width-16 shfl reduce gives
    // the row sum without writing exp'd fp32 back to smem.
    #pragma unroll
    for (int i = 0; i < 8; i++) {
        int idx = tid + (i << 8);
        int rr = idx >> 4, c = (idx & 15) << 3;
        float4 v0 = *reinterpret_cast<const float4*>(Cs + rr * 136 + c);
        float4 v1 = *reinterpret_cast<const float4*>(Cs + rr * 136 + c + 4);
        v0.x = __expf(v0.x * scale); v0.y = __expf(v0.y * scale);
        v0.z = __expf(v0.z * scale); v0.w = __expf(v0.w * scale);
        v1.x = __expf(v1.x * scale); v1.y = __expf(v1.y * scale);
        v1.z = __expf(v1.z * scale); v1.w = __expf(v1.w * scale);
        float ls = (v0.x + v0.y + v0.z + v0.w) + (v1.x + v1.y + v1.z + v1.w);
        #pragma unroll
        for (int o = 8; o > 0; o >>= 1)
            ls += __shfl_xor_sync(0xffffffffu, ls, o, 16);
        if ((tid & 15) == 0)
            g.part[(long long)bx * ((long long)g.nz * g.Mb) + z * g.Mb + row0 + rr] = ls;
        __half2 h0 = __floats2half2_rn(v0.x, v0.y);
        __half2 h1 = __floats2half2_rn(v0.z, v0.w);
        __half2 h2 = __floats2half2_rn(v1.x, v1.y);
        __half2 h3 = __floats2half2_rn(v1.z, v1.w);
        uint4 pk;
        pk.x = *(unsigned*)&h0; pk.y = *(unsigned*)&h1;
        pk.z = *(unsigned*)&h2; pk.w = *(unsigned*)&h3;
        *reinterpret_cast<uint4*>(Cb + (row0 + rr) * N + n0 + c) = pk;
    }
}

// ---- PV: fp32 out scaled by per-row 1/rowsum ----
template<int NG>
__global__ __launch_bounds__(256, 2)
void gemm_pv(GPack<NG> P)
{
    GEMM_PREAMBLE(NG)
    float* Cb = (float*)g.C + z * g.sC;
    if (tid < TM) biassm[tid] = g.rowscale[z * g.sR + row0 + tid];
    GEMM_MAINLOOP()

    #pragma unroll
    for (int i = 0; i < 16; i++) {
        int idx = tid + (i << 8);
        int rr = idx >> 5, c = (idx & 31) << 2;
        float4 v = *reinterpret_cast<const float4*>(Cs + rr * 136 + c);
        float rb = biassm[rr];
        v.x *= rb; v.y *= rb; v.z *= rb; v.w *= rb;
        *reinterpret_cast<float4*>(Cb + (row0 + rr) * N + n0 + c) = v;
    }
}

// ---------------- combined rowsum reduce for both attention dirs ----------
__global__ __launch_bounds__(256)
void rsum_inv2(const float* __restrict__ part1, float* __restrict__ inv1,
               const float* __restrict__ part2, float* __restrict__ inv2)
{
    int q = blockIdx.x * 256 + threadIdx.x;
    if (q < SEMROWS) {
        float s = 0.0f;
        #pragma unroll 4
        for (int i = 0; i < 32; i++) s += part1[(long long)i * SEMROWS + q];
        inv1[q] = 1.0f / s;
    } else {
        int q2 = q - SEMROWS;
        float s = 0.0f;
        #pragma unroll 4
        for (int i = 0; i < 16; i++) s += part2[(long long)i * SYNROWS + q2];
        inv2[q2] = 1.0f / s;
    }
}

// ---------------- combined fp32 -> fp16 conversion for both inputs --------
__global__ __launch_bounds__(256)
void cvt_both(const float* __restrict__ in1, __half* __restrict__ out1, int n1,
              const float* __restrict__ in2, __half* __restrict__ out2)
{
    int i = (blockIdx.x * 256 + threadIdx.x) * 4;
    const float* in;
    __half* out;
    if (i < n1) { in = in1; out = out1; }
    else        { in = in2 - n1; out = out2 - n1; }
    float4 v = *reinterpret_cast<const float4*>(in + i);
    H4 h; __half2* hp = (__half2*)&h;
    hp[0] = __floats2half2_rn(v.x, v.y);
    hp[1] = __floats2half2_rn(v.z, v.w);
    *reinterpret_cast<H4*>(out + i) = h;
}

// -------- batched transpose fp32 -> fp16 (all 6 weights in one launch) ----
struct WSet { const float* in[6]; };
__global__ __launch_bounds__(256)
void transpose_h6(WSet ws, __half* __restrict__ out)
{
    __shared__ float ts[32][33];
    const int R = HID, C = HID;
    const float* in = ws.in[blockIdx.z];
    __half* o = out + (long long)blockIdx.z * HID * HID;
    int tx = threadIdx.x & 31, ty = threadIdx.x >> 5;
    int c0 = blockIdx.x * 32, r0 = blockIdx.y * 32;
    #pragma unroll
    for (int j = 0; j < 4; j++)
        ts[ty + j * 8][tx] = in[(long long)(r0 + ty + j * 8) * C + c0 + tx];
    __syncthreads();
    #pragma unroll
    for (int j = 0; j < 4; j++)
        o[(long long)(c0 + ty + j * 8) * R + r0 + tx] = __float2half_rn(ts[tx][ty + j * 8]);
}

// ---------------- launcher ----------------
extern "C" void kernel_launch(void* const* d_in, const int* in_sizes, int n_in,
                              void* d_out, int out_size)
{
    const float* syn = (const float*)d_in[0];
    const float* sem = (const float*)d_in[1];
    const float* Wq1 = (const float*)d_in[2];  const float* bq1 = (const float*)d_in[3];
    const float* Wk1 = (const float*)d_in[4];  const float* bk1 = (const float*)d_in[5];
    const float* Wv1 = (const float*)d_in[6];  const float* bv1 = (const float*)d_in[7];
    const float* Wq2 = (const float*)d_in[8];  const float* bq2 = (const float*)d_in[9];
    const float* Wk2 = (const float*)d_in[10]; const float* bk2 = (const float*)d_in[11];
    const float* Wv2 = (const float*)d_in[12]; const float* bv2 = (const float*)d_in[13];

    float* o1 = (float*)d_out;                      // [4,2048,768]
    float* o2 = o1 + (long long)SEMROWS * HID;      // [4,4096,768]

    __half *semh, *synh, *wt, *q1, *k1, *q2, *k2, *v1t, *v2t, *p1, *p2;
    float *part1, *part2, *inv1, *inv2;
    cudaGetSymbolAddress((void**)&semh, g_semh);
    cudaGetSymbolAddress((void**)&synh, g_synh);
    cudaGetSymbolAddress((void**)&wt, g_wt);
    cudaGetSymbolAddress((void**)&q1, g_q1);
    cudaGetSymbolAddress((void**)&k1, g_k1);
    cudaGetSymbolAddress((void**)&q2, g_q2);
    cudaGetSymbolAddress((void**)&k2, g_k2);
    cudaGetSymbolAddress((void**)&v1t, g_v1t);
    cudaGetSymbolAddress((void**)&v2t, g_v2t);
    cudaGetSymbolAddress((void**)&p1, g_p1);
    cudaGetSymbolAddress((void**)&p2, g_p2);
    cudaGetSymbolAddress((void**)&part1, g_part1);
    cudaGetSymbolAddress((void**)&part2, g_part2);
    cudaGetSymbolAddress((void**)&inv1, g_inv1);
    cudaGetSymbolAddress((void**)&inv2, g_inv2);

    cudaFuncSetAttribute(gemm_proj<6>,
                         cudaFuncAttributeMaxDynamicSharedMemorySize, SMEM_GEMM);
    cudaFuncSetAttribute(gemm_exp<2>,
                         cudaFuncAttributeMaxDynamicSharedMemorySize, SMEM_GEMM);
    cudaFuncSetAttribute(gemm_pv<2>,
                         cudaFuncAttributeMaxDynamicSharedMemorySize, SMEM_GEMM);

    const float scale = 1.0f / sqrtf((float)HID);
    const long long WN = (long long)HID * HID;

    cvt_both<<<(SEMROWS + SYNROWS) * HID / 1024, 256>>>(
        sem, semh, SEMROWS * HID, syn, synh);
    WSet ws;
    ws.in[0] = Wq1; ws.in[1] = Wk1; ws.in[2] = Wv1;
    ws.in[3] = Wq2; ws.in[4] = Wk2; ws.in[5] = Wv2;
    transpose_h6<<<dim3(HID / 32, HID / 32, 6), 256>>>(ws, wt);

    auto mk = [&](const __half* A, const __half* B, const float* bias, void* C,
                  int N, int K, int ldb, long long sA, long long sB, long long sC,
                  float sc, float* part, int Mb, const float* rsc, long long sR,
                  int nx, int ny, int nz, int mode) {
        GArg a;
        a.A = A; a.B = B; a.bias = bias; a.C = C;
        a.N = N; a.K = K; a.ldb = ldb; a.sA = sA; a.sB = sB; a.sC = sC;
        a.scale = sc; a.part = part; a.Mb = Mb; a.rowscale = rsc; a.sR = sR;
        a.nx = nx; a.ny = ny; a.nz = nz; a.mode = mode;
        return a;
    };

    // ---- ALL 6 projections in one launch (3456 CTAs) ----
    {
        GPack<6> P;
        P.g[0] = mk(semh, wt + 0 * WN, bq1, q1, HID, HID, HID, 0, 0, 0, 1.0f,
                    nullptr, 0, nullptr, 0, HID/TN, SEMROWS/TM, 1, 1);
        P.g[1] = mk(semh, wt + 4 * WN, bk2, k2, HID, HID, HID, 0, 0, 0, 1.0f,
                    nullptr, 0, nullptr, 0, HID/TN, SEMROWS/TM, 1, 1);
        P.g[2] = mk(synh, wt + 1 * WN, bk1, k1, HID, HID, HID, 0, 0, 0, 1.0f,
                    nullptr, 0, nullptr, 0, HID/TN, SYNROWS/TM, 1, 1);
        P.g[3] = mk(synh, wt + 3 * WN, bq2, q2, HID, HID, HID, 0, 0, 0, 1.0f,
                    nullptr, 0, nullptr, 0, HID/TN, SYNROWS/TM, 1, 1);
        P.g[4] = mk(wt + 2 * WN, synh, bv1, v1t, SYNROWS, HID, HID, 0, 0, 0, 1.0f,
                    nullptr, 0, nullptr, 0, SYNROWS/TN, HID/TM, 1, 2);
        P.g[5] = mk(wt + 5 * WN, semh, bv2, v2t, SEMROWS, HID, HID, 0, 0, 0, 1.0f,
                    nullptr, 0, nullptr, 0, SEMROWS/TN, HID/TM, 1, 2);
        P.cum[0] = 384; P.cum[1] = 768; P.cum[2] = 1536;
        P.cum[3] = 2304; P.cum[4] = 3072; P.cum[5] = 3456;
        gemm_proj<6><<<3456, 256, SMEM_GEMM>>>(P);
    }

    // ---- scores+exp: 2 subs, one launch (2048 + 2048 = 4096 CTAs) ----
    {
        GPack<2> P;
        P.g[0] = mk(q1, k1, nullptr, p1, SSYN, HID, HID,
                    (long long)SSEM*HID, (long long)SSYN*HID, (long long)SSEM*SSYN,
                    scale, part1, SSEM, nullptr, 0, SSYN/TN, SSEM/TM, BATCH, 0);
        P.g[1] = mk(q2, k2, nullptr, p2, SSEM, HID, HID,
                    (long long)SSYN*HID, (long long)SSEM*HID, (long long)SSYN*SSEM,
                    scale, part2, SSYN, nullptr, 0, SSEM/TN, SSYN/TM, BATCH, 0);
        P.cum[0] = 2048; P.cum[1] = 4096;
        gemm_exp<2><<<4096, 256, SMEM_GEMM>>>(P);
    }

    // ---- both inverse row-sum sets in one launch ----
    rsum_inv2<<<(SEMROWS + SYNROWS) / 256, 256>>>(part1, inv1, part2, inv2);

    // ---- PV: 2 subs, one launch (1152 CTAs) ----
    {
        GPack<2> P;
        P.g[0] = mk(p1, v1t, nullptr, o1, HID, SSYN, SYNROWS,
                    (long long)SSEM*SSYN, (long long)SSYN, (long long)SSEM*HID,
                    1.0f, nullptr, 0, inv1, (long long)SSEM, HID/TN, SSEM/TM, BATCH, 0);
        P.g[1] = mk(p2, v2t, nullptr, o2, HID, SSEM, SEMROWS,
                    (long long)SSYN*SSEM, (long long)SSEM, (long long)SSYN*HID,
                    1.0f, nullptr, 0, inv2, (long long)SSYN, HID/TN, SSYN/TM, BATCH, 0);
        P.cum[0] = 384; P.cum[1] = 1152;
        gemm_pv<2><<<1152, 256, SMEM_GEMM>>>(P);
    }
}

// round 14
// speedup vs baseline: 1.1855x; 1.0024x over previous
#include <cuda_runtime.h>
#include <cuda_fp16.h>
#include <mma.h>
#include <math.h>
#include <stdint.h>

using namespace nvcuda;

// ---------------- problem constants ----------------
#define HID    768
#define BATCH  4
#define SSYN   4096
#define SSEM   2048
#define SEMROWS 8192     // BATCH*SSEM
#define SYNROWS 16384    // BATCH*SSYN

// ---------------- scratch (device globals; no allocations allowed) --------
__device__ __half g_semh[SEMROWS*HID];
__device__ __half g_synh[SYNROWS*HID];
__device__ __half g_wt[6*HID*HID];        // transposed weights [out,in] -> [N,K]
__device__ __half g_q1[SEMROWS*HID];      // PRE-SCALED by 1/sqrt(H)
__device__ __half g_k1[SYNROWS*HID];
__device__ __half g_q2[SYNROWS*HID];      // PRE-SCALED by 1/sqrt(H)
__device__ __half g_k2[SEMROWS*HID];
__device__ __half g_v1t[HID*SYNROWS];     // V1^T [768, 16384]
__device__ __half g_v2t[HID*SEMROWS];     // V2^T [768, 8192]
__device__ __half g_p1[(long long)BATCH*SSEM*SSYN];   // fp16 E = exp(scores)
__device__ __half g_p2[(long long)BATCH*SSYN*SSEM];
__device__ float  g_part1[32 * SEMROWS];  // per-n-tile row partial sums
__device__ float  g_part2[16 * SYNROWS];
__device__ float  g_inv1[SEMROWS];        // 1 / rowsum
__device__ float  g_inv2[SYNROWS];

struct H4 { __half2 a, b; };

// ---- fp16 wmma GEMM, 128x128x64 tile, 2-stage cp.async double buffer ----
constexpr int TM = 128, TN = 128, TK = 64;
constexpr int KP = 72;                        // padded halfs per tile row (144B)
constexpr int TILE_H = 128 * KP;
constexpr int STAGE_H = 2 * TILE_H;
constexpr int STAGE_BYTES = STAGE_H * 2;      // 36864
constexpr int SMEM_GEMM = 2 * STAGE_BYTES + 512;  // 74240 B

// ---- fp16-accum score GEMM, 128x256x64 CTA tile, 64x64 warp tile ----
constexpr int EN = 256;                       // score kernel N tile
constexpr int A_H2 = 128 * KP;                // 9216 halfs
constexpr int B_H2 = 256 * KP;                // 18432 halfs
constexpr int STAGE_H2 = A_H2 + B_H2;         // 27648 halfs = 55296 B
constexpr int SMEM_EXP = 2 * STAGE_H2 * 2 + 512;  // 111104 B (2 CTA/SM ok)

struct GArg {
    const __half* A;
    const __half* B;
    const float*  bias;
    void*         C;
    int  N, K, ldb;
    long long sA, sB, sC;
    float scale;
    float* part;           // exp kernel
    int    Mb;             // exp kernel: rows per batch
    const float* rowscale; // pv kernel
    long long sR;
    int nx, ny, nz;        // sub-grid dims
    int mode;              // proj kernel: 1=col bias, 2=row bias
};
template<int NG> struct GPack { GArg g[NG]; int cum[NG]; };

__device__ __forceinline__ void cpa16(__half* dst, const __half* src) {
    unsigned d = (unsigned)__cvta_generic_to_shared(dst);
    asm volatile("cp.async.cg.shared.global [%0], [%1], 16;" :: "r"(d), "l"(src));
}

#define GEMM_MAINLOOP()                                                          \
    wmma::fragment<wmma::matrix_a, 16, 16, 16, __half, wmma::row_major> af[4];   \
    wmma::fragment<wmma::matrix_b, 16, 16, 16, __half, wmma::col_major> bf[2];   \
    wmma::fragment<wmma::accumulator, 16, 16, 16, float> cf[4][2];               \
    _Pragma("unroll")                                                            \
    for (int i = 0; i < 4; i++)                                                  \
        _Pragma("unroll")                                                        \
        for (int j = 0; j < 2; j++)                                              \
            wmma::fill_fragment(cf[i][j], 0.0f);                                 \
    const int nt = K / TK;                                                       \
    auto load_tiles = [&](int t, int stage) {                                    \
        const __half* Ag = Ab + (long long)t * TK;                               \
        __half* da = sm + stage * STAGE_H;                                       \
        _Pragma("unroll")                                                        \
        for (int i = 0; i < 4; i++) {                                            \
            int idx = tid + (i << 8);                                            \
            int rr = idx >> 3, c = (idx & 7) << 3;                               \
            cpa16(da + rr * KP + c, Ag + (long long)rr * K + c);                 \
        }                                                                        \
        const __half* Bg = Bb + (long long)t * TK;                               \
        __half* db = da + TILE_H;                                                \
        _Pragma("unroll")                                                        \
        for (int i = 0; i < 4; i++) {                                            \
            int idx = tid + (i << 8);                                            \
            int rr = idx >> 3, c = (idx & 7) << 3;                               \
            cpa16(db + rr * KP + c, Bg + (long long)rr * ldb + c);               \
        }                                                                        \
    };                                                                           \
    load_tiles(0, 0);                                                            \
    asm volatile("cp.async.commit_group;");                                      \
    for (int t = 0; t < nt; t++) {                                               \
        if (t + 1 < nt) load_tiles(t + 1, (t + 1) & 1);                          \
        asm volatile("cp.async.commit_group;");                                  \
        if (t + 1 < nt)                                                          \
            asm volatile("cp.async.wait_group 1;");                              \
        else                                                                     \
            asm volatile("cp.async.wait_group 0;");                              \
        __syncthreads();                                                         \
        const __half* Ad = sm + (t & 1) * STAGE_H;                               \
        const __half* Bd = Ad + TILE_H;                                          \
        _Pragma("unroll")                                                        \
        for (int kk = 0; kk < 4; kk++) {                                         \
            _Pragma("unroll")                                                    \
            for (int i = 0; i < 4; i++)                                          \
                wmma::load_matrix_sync(af[i], Ad + (wm * 64 + i * 16) * KP + kk * 16, KP); \
            _Pragma("unroll")                                                    \
            for (int j = 0; j < 2; j++)                                          \
                wmma::load_matrix_sync(bf[j], Bd + (wn * 32 + j * 16) * KP + kk * 16, KP); \
            _Pragma("unroll")                                                    \
            for (int i = 0; i < 4; i++)                                          \
                _Pragma("unroll")                                                \
                for (int j = 0; j < 2; j++)                                      \
                    wmma::mma_sync(cf[i][j], af[i], bf[j], cf[i][j]);            \
        }                                                                        \
        __syncthreads();                                                         \
    }                                                                            \
    float* Cs = (float*)sm;                                                      \
    _Pragma("unroll")                                                            \
    for (int i = 0; i < 4; i++)                                                  \
        _Pragma("unroll")                                                        \
        for (int j = 0; j < 2; j++)                                              \
            wmma::store_matrix_sync(Cs + (wm * 64 + i * 16) * 136 + wn * 32 + j * 16, \
                                    cf[i][j], 136, wmma::mem_row_major);         \
    __syncthreads();

#define GEMM_PREAMBLE(NG)                                                        \
    extern __shared__ __align__(16) __half sm[];                                 \
    int flat = blockIdx.x, gi = 0;                                               \
    _Pragma("unroll")                                                            \
    for (int i = 0; i + 1 < NG; i++) if (flat >= P.cum[i]) gi = i + 1;           \
    const GArg& g = P.g[gi];                                                     \
    int r = flat - (gi ? P.cum[gi - 1] : 0);                                     \
    const int bx = r % g.nx; r /= g.nx;                                          \
    const int by = r % g.ny;                                                     \
    const long long z = r / g.ny;                                                \
    const int tid = threadIdx.x;                                                 \
    const int wid = tid >> 5;                                                    \
    const int wm  = wid & 1;                                                     \
    const int wn  = wid >> 1;                                                    \
    const int N = g.N, K = g.K, ldb = g.ldb;                                     \
    const float scale = g.scale;                                                 \
    const long long row0 = (long long)by * TM;                                   \
    const __half* Ab = g.A + z * g.sA + row0 * K;

// ---- projections: fp16 out, runtime col(1)/row(2) bias, x scale ----
template<int NG>
__global__ __launch_bounds__(256, 2)
void gemm_proj(GPack<NG> P)
{
    GEMM_PREAMBLE(NG)
    const int n0 = bx * TN;
    const __half* Bb = g.B + z * g.sB + (long long)n0 * ldb;
    float* biassm = (float*)((char*)sm + 2 * STAGE_BYTES);
    __half* Cb = (__half*)g.C + z * g.sC;
    const int mode = g.mode;
    if (mode == 1) { if (tid < TN) biassm[tid] = g.bias[n0 + tid]; }
    else           { if (tid < TM) biassm[tid] = g.bias[row0 + tid]; }
    GEMM_MAINLOOP()

    #pragma unroll
    for (int i = 0; i < 8; i++) {
        int idx = tid + (i << 8);
        int rr = idx >> 4, c = (idx & 15) << 3;
        float4 v0 = *reinterpret_cast<const float4*>(Cs + rr * 136 + c);
        float4 v1 = *reinterpret_cast<const float4*>(Cs + rr * 136 + c + 4);
        if (mode == 1) {
            v0.x += biassm[c + 0]; v0.y += biassm[c + 1];
            v0.z += biassm[c + 2]; v0.w += biassm[c + 3];
            v1.x += biassm[c + 4]; v1.y += biassm[c + 5];
            v1.z += biassm[c + 6]; v1.w += biassm[c + 7];
        } else {
            float rb = biassm[rr];
            v0.x += rb; v0.y += rb; v0.z += rb; v0.w += rb;
            v1.x += rb; v1.y += rb; v1.z += rb; v1.w += rb;
        }
        v0.x *= scale; v0.y *= scale; v0.z *= scale; v0.w *= scale;
        v1.x *= scale; v1.y *= scale; v1.z *= scale; v1.w *= scale;
        __half2 h0 = __floats2half2_rn(v0.x, v0.y);
        __half2 h1 = __floats2half2_rn(v0.z, v0.w);
        __half2 h2 = __floats2half2_rn(v1.x, v1.y);
        __half2 h3 = __floats2half2_rn(v1.z, v1.w);
        uint4 pk;
        pk.x = *(unsigned*)&h0; pk.y = *(unsigned*)&h1;
        pk.z = *(unsigned*)&h2; pk.w = *(unsigned*)&h3;
        *reinterpret_cast<uint4*>(Cb + (row0 + rr) * N + n0 + c) = pk;
    }
}

// ---- scores: fp16-accum 128x256 tile, 64x64 warp tile, exp on fragments ----
// Q operand is PRE-SCALED, so accumulator holds scaled scores directly.
template<int NG>
__global__ __launch_bounds__(256, 2)
void gemm_exp(GPack<NG> P)
{
    extern __shared__ __align__(16) __half sm[];
    int flat = blockIdx.x, gi = 0;
    #pragma unroll
    for (int i = 0; i + 1 < NG; i++) if (flat >= P.cum[i]) gi = i + 1;
    const GArg& g = P.g[gi];
    int r = flat - (gi ? P.cum[gi - 1] : 0);
    const int bx = r % g.nx; r /= g.nx;
    const int by = r % g.ny;
    const long long z = r / g.ny;
    const int tid = threadIdx.x;
    const int wid = tid >> 5;
    const int wm  = wid & 1;               // warp row 0..1 (64 rows)
    const int wn  = wid >> 1;              // warp col 0..3 (64 cols)
    const int N = g.N, K = g.K, ldb = g.ldb;
    const int n0 = bx * EN;
    const long long row0 = (long long)by * TM;
    const __half* Ab = g.A + z * g.sA + row0 * K;
    const __half* Bb = g.B + z * g.sB + (long long)n0 * ldb;
    __half* Cb = (__half*)g.C + z * g.sC;

    wmma::fragment<wmma::matrix_a, 16, 16, 16, __half, wmma::row_major> af[4];
    wmma::fragment<wmma::matrix_b, 16, 16, 16, __half, wmma::col_major> bf[4];
    wmma::fragment<wmma::accumulator, 16, 16, 16, __half> cf[4][4];
    #pragma unroll
    for (int i = 0; i < 4; i++)
        #pragma unroll
        for (int j = 0; j < 4; j++)
            wmma::fill_fragment(cf[i][j], __float2half(0.0f));

    const int nt = K / TK;

    auto load_tiles = [&](int t, int stage) {
        const __half* Ag = Ab + (long long)t * TK;
        __half* da = sm + stage * STAGE_H2;
        #pragma unroll
        for (int i = 0; i < 4; i++) {                 // A: 128x64
            int idx = tid + (i << 8);
            int rr = idx >> 3, c = (idx & 7) << 3;
            cpa16(da + rr * KP + c, Ag + (long long)rr * K + c);
        }
        const __half* Bg = Bb + (long long)t * TK;
        __half* db = da + A_H2;
        #pragma unroll
        for (int i = 0; i < 8; i++) {                 // B: 256x64
            int idx = tid + (i << 8);
            int rr = idx >> 3, c = (idx & 7) << 3;
            cpa16(db + rr * KP + c, Bg + (long long)rr * ldb + c);
        }
    };

    load_tiles(0, 0);
    asm volatile("cp.async.commit_group;");

    for (int t = 0; t < nt; t++) {
        if (t + 1 < nt) load_tiles(t + 1, (t + 1) & 1);
        asm volatile("cp.async.commit_group;");
        if (t + 1 < nt)
            asm volatile("cp.async.wait_group 1;");
        else
            asm volatile("cp.async.wait_group 0;");
        __syncthreads();

        const __half* Ad = sm + (t & 1) * STAGE_H2;
        const __half* Bd = Ad + A_H2;
        #pragma unroll
        for (int kk = 0; kk < 4; kk++) {
            #pragma unroll
            for (int i = 0; i < 4; i++)
                wmma::load_matrix_sync(af[i], Ad + (wm * 64 + i * 16) * KP + kk * 16, KP);
            #pragma unroll
            for (int j = 0; j < 4; j++)
                wmma::load_matrix_sync(bf[j], Bd + (wn * 64 + j * 16) * KP + kk * 16, KP);
            #pragma unroll
            for (int i = 0; i < 4; i++)
                #pragma unroll
                for (int j = 0; j < 4; j++)
                    wmma::mma_sync(cf[i][j], af[i], bf[j], cf[i][j]);
        }
        __syncthreads();
    }

    // exp elementwise on fragments (position-independent => legal)
    #pragma unroll
    for (int i = 0; i < 4; i++)
        #pragma unroll
        for (int j = 0; j < 4; j++)
            #pragma unroll
            for (int e = 0; e < cf[i][j].num_elements; e++)
                cf[i][j].x[e] = __float2half_rn(__expf(__half2float(cf[i][j].x[e])));

    // stage E (half) -> smem, ldm = 264 halfs (528B)
    __half* Csh = sm;
    #pragma unroll
    for (int i = 0; i < 4; i++)
        #pragma unroll
        for (int j = 0; j < 4; j++)
            wmma::store_matrix_sync(Csh + (wm * 64 + i * 16) * 264 + wn * 64 + j * 16,
                                    cf[i][j], 264, wmma::mem_row_major);
    __syncthreads();

    // write E + full-warp shfl row sums (32 lanes span one row of 256)
    #pragma unroll
    for (int i = 0; i < 16; i++) {
        int idx = tid + (i << 8);
        int rr = idx >> 5, c = (idx & 31) << 3;
        uint4 pk = *reinterpret_cast<const uint4*>(Csh + rr * 264 + c);
        __half2* hp = (__half2*)&pk;
        float2 f0 = __half22float2(hp[0]);
        float2 f1 = __half22float2(hp[1]);
        float2 f2 = __half22float2(hp[2]);
        float2 f3 = __half22float2(hp[3]);
        float ls = (f0.x + f0.y) + (f1.x + f1.y) + (f2.x + f2.y) + (f3.x + f3.y);
        #pragma unroll
        for (int o = 16; o > 0; o >>= 1)
            ls += __shfl_xor_sync(0xffffffffu, ls, o);
        if ((tid & 31) == 0)
            g.part[(long long)bx * ((long long)g.nz * g.Mb) + z * g.Mb + row0 + rr] = ls;
        *reinterpret_cast<uint4*>(Cb + (row0 + rr) * N + n0 + c) = pk;
    }
}

// ---- PV: fp32 out scaled by per-row 1/rowsum ----
template<int NG>
__global__ __launch_bounds__(256, 2)
void gemm_pv(GPack<NG> P)
{
    GEMM_PREAMBLE(NG)
    const int n0 = bx * TN;
    const __half* Bb = g.B + z * g.sB + (long long)n0 * ldb;
    float* biassm = (float*)((char*)sm + 2 * STAGE_BYTES);
    float* Cb = (float*)g.C + z * g.sC;
    if (tid < TM) biassm[tid] = g.rowscale[z * g.sR + row0 + tid];
    GEMM_MAINLOOP()
    (void)scale;

    #pragma unroll
    for (int i = 0; i < 16; i++) {
        int idx = tid + (i << 8);
        int rr = idx >> 5, c = (idx & 31) << 2;
        float4 v = *reinterpret_cast<const float4*>(Cs + rr * 136 + c);
        float rb = biassm[rr];
        v.x *= rb; v.y *= rb; v.z *= rb; v.w *= rb;
        *reinterpret_cast<float4*>(Cb + (row0 + rr) * N + n0 + c) = v;
    }
}

// ---------------- combined rowsum reduce for both attention dirs ----------
__global__ __launch_bounds__(256)
void rsum_inv2(const float* __restrict__ part1, float* __restrict__ inv1,
               const float* __restrict__ part2, float* __restrict__ inv2)
{
    int q = blockIdx.x * 256 + threadIdx.x;
    if (q < SEMROWS) {
        float s = 0.0f;
        #pragma unroll 4
        for (int i = 0; i < 16; i++) s += part1[(long long)i * SEMROWS + q];
        inv1[q] = 1.0f / s;
    } else {
        int q2 = q - SEMROWS;
        float s = 0.0f;
        #pragma unroll 4
        for (int i = 0; i < 8; i++) s += part2[(long long)i * SYNROWS + q2];
        inv2[q2] = 1.0f / s;
    }
}

// ---------------- combined fp32 -> fp16 conversion for both inputs --------
__global__ __launch_bounds__(256)
void cvt_both(const float* __restrict__ in1, __half* __restrict__ out1, int n1,
              const float* __restrict__ in2, __half* __restrict__ out2)
{
    int i = (blockIdx.x * 256 + threadIdx.x) * 4;
    const float* in;
    __half* out;
    if (i < n1) { in = in1; out = out1; }
    else        { in = in2 - n1; out = out2 - n1; }
    float4 v = *reinterpret_cast<const float4*>(in + i);
    H4 h; __half2* hp = (__half2*)&h;
    hp[0] = __floats2half2_rn(v.x, v.y);
    hp[1] = __floats2half2_rn(v.z, v.w);
    *reinterpret_cast<H4*>(out + i) = h;
}

// -------- batched transpose fp32 -> fp16 (all 6 weights in one launch) ----
struct WSet { const float* in[6]; };
__global__ __launch_bounds__(256)
void transpose_h6(WSet ws, __half* __restrict__ out)
{
    __shared__ float ts[32][33];
    const int R = HID, C = HID;
    const float* in = ws.in[blockIdx.z];
    __half* o = out + (long long)blockIdx.z * HID * HID;
    int tx = threadIdx.x & 31, ty = threadIdx.x >> 5;
    int c0 = blockIdx.x * 32, r0 = blockIdx.y * 32;
    #pragma unroll
    for (int j = 0; j < 4; j++)
        ts[ty + j * 8][tx] = in[(long long)(r0 + ty + j * 8) * C + c0 + tx];
    __syncthreads();
    #pragma unroll
    for (int j = 0; j < 4; j++)
        o[(long long)(c0 + ty + j * 8) * R + r0 + tx] = __float2half_rn(ts[tx][ty + j * 8]);
}

// ---------------- launcher ----------------
extern "C" void kernel_launch(void* const* d_in, const int* in_sizes, int n_in,
                              void* d_out, int out_size)
{
    const float* syn = (const float*)d_in[0];
    const float* sem = (const float*)d_in[1];
    const float* Wq1 = (const float*)d_in[2];  const float* bq1 = (const float*)d_in[3];
    const float* Wk1 = (const float*)d_in[4];  const float* bk1 = (const float*)d_in[5];
    const float* Wv1 = (const float*)d_in[6];  const float* bv1 = (const float*)d_in[7];
    const float* Wq2 = (const float*)d_in[8];  const float* bq2 = (const float*)d_in[9];
    const float* Wk2 = (const float*)d_in[10]; const float* bk2 = (const float*)d_in[11];
    const float* Wv2 = (const float*)d_in[12]; const float* bv2 = (const float*)d_in[13];

    float* o1 = (float*)d_out;                      // [4,2048,768]
    float* o2 = o1 + (long long)SEMROWS * HID;      // [4,4096,768]

    __half *semh, *synh, *wt, *q1, *k1, *q2, *k2, *v1t, *v2t, *p1, *p2;
    float *part1, *part2, *inv1, *inv2;
    cudaGetSymbolAddress((void**)&semh, g_semh);
    cudaGetSymbolAddress((void**)&synh, g_synh);
    cudaGetSymbolAddress((void**)&wt, g_wt);
    cudaGetSymbolAddress((void**)&q1, g_q1);
    cudaGetSymbolAddress((void**)&k1, g_k1);
    cudaGetSymbolAddress((void**)&q2, g_q2);
    cudaGetSymbolAddress((void**)&k2, g_k2);
    cudaGetSymbolAddress((void**)&v1t, g_v1t);
    cudaGetSymbolAddress((void**)&v2t, g_v2t);
    cudaGetSymbolAddress((void**)&p1, g_p1);
    cudaGetSymbolAddress((void**)&p2, g_p2);
    cudaGetSymbolAddress((void**)&part1, g_part1);
    cudaGetSymbolAddress((void**)&part2, g_part2);
    cudaGetSymbolAddress((void**)&inv1, g_inv1);
    cudaGetSymbolAddress((void**)&inv2, g_inv2);

    cudaFuncSetAttribute(gemm_proj<6>,
                         cudaFuncAttributeMaxDynamicSharedMemorySize, SMEM_GEMM);
    cudaFuncSetAttribute(gemm_exp<2>,
                         cudaFuncAttributeMaxDynamicSharedMemorySize, SMEM_EXP);
    cudaFuncSetAttribute(gemm_pv<2>,
                         cudaFuncAttributeMaxDynamicSharedMemorySize, SMEM_GEMM);

    const float scale = 1.0f / sqrtf((float)HID);
    const long long WN = (long long)HID * HID;

    cvt_both<<<(SEMROWS + SYNROWS) * HID / 1024, 256>>>(
        sem, semh, SEMROWS * HID, syn, synh);
    WSet ws;
    ws.in[0] = Wq1; ws.in[1] = Wk1; ws.in[2] = Wv1;
    ws.in[3] = Wq2; ws.in[4] = Wk2; ws.in[5] = Wv2;
    transpose_h6<<<dim3(HID / 32, HID / 32, 6), 256>>>(ws, wt);

    auto mk = [&](const __half* A, const __half* B, const float* bias, void* C,
                  int N, int K, int ldb, long long sA, long long sB, long long sC,
                  float sc, float* part, int Mb, const float* rsc, long long sR,
                  int nx, int ny, int nz, int mode) {
        GArg a;
        a.A = A; a.B = B; a.bias = bias; a.C = C;
        a.N = N; a.K = K; a.ldb = ldb; a.sA = sA; a.sB = sB; a.sC = sC;
        a.scale = sc; a.part = part; a.Mb = Mb; a.rowscale = rsc; a.sR = sR;
        a.nx = nx; a.ny = ny; a.nz = nz; a.mode = mode;
        return a;
    };

    // ---- ALL 6 projections in one launch; q1/q2 pre-scaled by 1/sqrt(H) ----
    {
        GPack<6> P;
        P.g[0] = mk(semh, wt + 0 * WN, bq1, q1, HID, HID, HID, 0, 0, 0, scale,
                    nullptr, 0, nullptr, 0, HID/TN, SEMROWS/TM, 1, 1);
        P.g[1] = mk(semh, wt + 4 * WN, bk2, k2, HID, HID, HID, 0, 0, 0, 1.0f,
                    nullptr, 0, nullptr, 0, HID/TN, SEMROWS/TM, 1, 1);
        P.g[2] = mk(synh, wt + 1 * WN, bk1, k1, HID, HID, HID, 0, 0, 0, 1.0f,
                    nullptr, 0, nullptr, 0, HID/TN, SYNROWS/TM, 1, 1);
        P.g[3] = mk(synh, wt + 3 * WN, bq2, q2, HID, HID, HID, 0, 0, 0, scale,
                    nullptr, 0, nullptr, 0, HID/TN, SYNROWS/TM, 1, 1);
        P.g[4] = mk(wt + 2 * WN, synh, bv1, v1t, SYNROWS, HID, HID, 0, 0, 0, 1.0f,
                    nullptr, 0, nullptr, 0, SYNROWS/TN, HID/TM, 1, 2);
        P.g[5] = mk(wt + 5 * WN, semh, bv2, v2t, SEMROWS, HID, HID, 0, 0, 0, 1.0f,
                    nullptr, 0, nullptr, 0, SEMROWS/TN, HID/TM, 1, 2);
        P.cum[0] = 384; P.cum[1] = 768; P.cum[2] = 1536;
        P.cum[3] = 2304; P.cum[4] = 3072; P.cum[5] = 3456;
        gemm_proj<6><<<3456, 256, SMEM_GEMM>>>(P);
    }

    // ---- scores+exp: fp16-accum 128x256 tiles, 1024+1024 CTAs ----
    {
        GPack<2> P;
        P.g[0] = mk(q1, k1, nullptr, p1, SSYN, HID, HID,
                    (long long)SSEM*HID, (long long)SSYN*HID, (long long)SSEM*SSYN,
                    1.0f, part1, SSEM, nullptr, 0, SSYN/EN, SSEM/TM, BATCH, 0);
        P.g[1] = mk(q2, k2, nullptr, p2, SSEM, HID, HID,
                    (long long)SSYN*HID, (long long)SSEM*HID, (long long)SSYN*SSEM,
                    1.0f, part2, SSYN, nullptr, 0, SSEM/EN, SSYN/TM, BATCH, 0);
        P.cum[0] = 1024; P.cum[1] = 2048;   // 16*16*4  and  8*32*4
        gemm_exp<2><<<2048, 256, SMEM_EXP>>>(P);
    }

    // ---- both inverse row-sum sets in one launch ----
    rsum_inv2<<<(SEMROWS + SYNROWS) / 256, 256>>>(part1, inv1, part2, inv2);

    // ---- PV: 2 subs, one launch (1152 CTAs) ----
    {
        GPack<2> P;
        P.g[0] = mk(p1, v1t, nullptr, o1, HID, SSYN, SYNROWS,
                    (long long)SSEM*SSYN, (long long)SSYN, (long long)SSEM*HID,
                    1.0f, nullptr, 0, inv1, (long long)SSEM, HID/TN, SSEM/TM, BATCH, 0);
        P.g[1] = mk(p2, v2t, nullptr, o2, HID, SSEM, SEMROWS,
                    (long long)SSYN*SSEM, (long long)SSEM, (long long)SSYN*HID,
                    1.0f, nullptr, 0, inv2, (long long)SSYN, HID/TN, SSYN/TM, BATCH, 0);
        P.cum[0] = 384; P.cum[1] = 1152;
        gemm_pv<2><<<1152, 256, SMEM_GEMM>>>(P);
    }
}